// round 6
// baseline (speedup 1.0000x reference)
#include <cuda_runtime.h>
#include <cuda_bf16.h>
#include <cstdint>
#include <math.h>

// Problem constants
#define BB   2
#define SS   2048
#define DD   1024
#define HH   16
#define DKK  64
#define DFFF 4096
#define MM   (BB * SS)          // 4096 rows
#define EPSF 1.1920929e-07f

// ---------------------------------------------------------------------------
// Scratch (device globals — no cudaMalloc allowed)
// ---------------------------------------------------------------------------
__device__ float g_h  [MM * DD];
__device__ float g_q  [MM * DD];
__device__ float g_k  [MM * DD];
__device__ float g_v  [MM * DD];
__device__ float g_o  [MM * DD];
__device__ float g_x2 [MM * DD];
__device__ float g_h2 [MM * DD];
__device__ float g_ff [MM * DFFF];
// tf32-pre-rounded weights
__device__ float g_rwq[DD * DD];
__device__ float g_rwk[DD * DD];
__device__ float g_rwv[DD * DD];
__device__ float g_rwo[DD * DD];
__device__ float g_rw1[DD * DFFF];
__device__ float g_rw2[DFFF * DD];

// ---------------------------------------------------------------------------
// helpers
// ---------------------------------------------------------------------------
__device__ __forceinline__ uint32_t smem_u32(const void* p) {
    uint32_t a;
    asm("{ .reg .u64 t; cvta.to.shared.u64 t, %1; cvt.u32.u64 %0, t; }"
        : "=r"(a) : "l"(p));
    return a;
}
__device__ __forceinline__ void cp16(uint32_t saddr, const void* g) {
    asm volatile("cp.async.cg.shared.global [%0], [%1], 16;" :: "r"(saddr), "l"(g));
}
__device__ __forceinline__ uint32_t f2tf32(float f) {
    uint32_t r;
    asm("cvt.rna.tf32.f32 %0, %1;" : "=r"(r) : "f"(f));
    return r;
}
__device__ __forceinline__ float rtf(float f) {
    return __uint_as_float(f2tf32(f));
}
__device__ __forceinline__ void mma_tf32(
    float* c, const uint32_t* a, const uint32_t* b)
{
    asm volatile(
        "mma.sync.aligned.m16n8k8.row.col.f32.tf32.tf32.f32 "
        "{%0,%1,%2,%3}, {%4,%5,%6,%7}, {%8,%9}, {%0,%1,%2,%3};"
        : "+f"(c[0]), "+f"(c[1]), "+f"(c[2]), "+f"(c[3])
        : "r"(a[0]), "r"(a[1]), "r"(a[2]), "r"(a[3]), "r"(b[0]), "r"(b[1]));
}

// ---------------------------------------------------------------------------
// Fused tf32 rounding for all 6 weights in one launch.
// Segments (in float4): wq,wk,wv,wo = 256Ki each; w1,w2 = 1Mi each.
// ---------------------------------------------------------------------------
#define SEG  262144                 // (DD*DD)/4
#define SEGF 1048576                // (DD*DFFF)/4
__global__ void __launch_bounds__(256) round_all_kernel(
    const float* __restrict__ s0, const float* __restrict__ s1,
    const float* __restrict__ s2, const float* __restrict__ s3,
    const float* __restrict__ s4, const float* __restrict__ s5,
    float* __restrict__ d0, float* __restrict__ d1,
    float* __restrict__ d2, float* __restrict__ d3,
    float* __restrict__ d4, float* __restrict__ d5)
{
    long long i = (long long)blockIdx.x * 256 + threadIdx.x;
    const float4* src;
    float4* dst;
    long long off;
    if      (i < 1 * SEG) { src = (const float4*)s0; dst = (float4*)d0; off = i; }
    else if (i < 2 * SEG) { src = (const float4*)s1; dst = (float4*)d1; off = i - 1 * SEG; }
    else if (i < 3 * SEG) { src = (const float4*)s2; dst = (float4*)d2; off = i - 2 * SEG; }
    else if (i < 4 * SEG) { src = (const float4*)s3; dst = (float4*)d3; off = i - 3 * SEG; }
    else if (i < 4 * SEG + SEGF) { src = (const float4*)s4; dst = (float4*)d4; off = i - 4 * SEG; }
    else                   { src = (const float4*)s5; dst = (float4*)d5; off = i - 4 * SEG - SEGF; }
    float4 v = src[off];
    v.x = rtf(v.x); v.y = rtf(v.y); v.z = rtf(v.z); v.w = rtf(v.w);
    dst[off] = v;
}
#define ROUND_BLOCKS ((4 * SEG + 2 * SEGF) / 256)

// ---------------------------------------------------------------------------
// GEMM v2: CTA tile 128x256, BK=16, 256 threads, 8 warps (2m x 4n),
// warp tile 64x64. 3-stage cp.async pipeline, dynamic smem.
// Inputs must be tf32-pre-rounded. Runtime epi: 0=bias,1=+relu,2=+residual.
// ---------------------------------------------------------------------------
#define BM 128
#define BN 256
#define BK 16
#define ASTRIDE 20     // floats
#define BSTRIDE 264    // floats (264 mod 32 == 8)
#define A_FLTS (BM * ASTRIDE)            // 2560
#define B_FLTS (BK * BSTRIDE)            // 4224
#define STG_FLTS (A_FLTS + B_FLTS)       // 6784
#define GEMM2_SMEM (3 * STG_FLTS * 4)    // 81408 bytes

__device__ __forceinline__ void g2_copy(
    float* sA, float* sB, const float* __restrict__ A,
    const float* __restrict__ B, int brow, int bcol, int k0, int Nd, int Kd,
    int tid)
{
    // A: 128 rows x 16 floats = 512 float4
    #pragma unroll
    for (int i = 0; i < 2; i++) {
        int e = tid + i * 256;
        int m = e >> 2, c4 = (e & 3) << 2;
        cp16(smem_u32(sA + m * ASTRIDE + c4),
             A + (size_t)(brow + m) * Kd + k0 + c4);
    }
    // B: 16 rows x 256 floats = 1024 float4
    #pragma unroll
    for (int i = 0; i < 4; i++) {
        int e = tid + i * 256;
        int kr = e >> 6, c4 = (e & 63) << 2;
        cp16(smem_u32(sB + kr * BSTRIDE + c4),
             B + (size_t)(k0 + kr) * Nd + bcol + c4);
    }
    asm volatile("cp.async.commit_group;");
}

__device__ __forceinline__ void gemm2_core(
    const float* __restrict__ A, const float* __restrict__ B,
    const float* __restrict__ bias, const float* __restrict__ res,
    float* __restrict__ C, int Nd, int Kd, int brow, int bcol,
    int epi, bool rnd, float* sm)
{
    float* sA[3] = { sm, sm + STG_FLTS, sm + 2 * STG_FLTS };
    float* sB[3] = { sm + A_FLTS, sm + STG_FLTS + A_FLTS, sm + 2 * STG_FLTS + A_FLTS };

    const int tid  = threadIdx.x;
    const int lane = tid & 31;
    const int wid  = tid >> 5;
    const int warp_m = (wid >> 2) * 64;   // 0 or 64
    const int warp_n = (wid & 3) * 64;    // 0,64,128,192
    const int tg  = lane >> 2;
    const int tig = lane & 3;
    const int KT = Kd / BK;

    float acc[4][8][4];
    #pragma unroll
    for (int mi = 0; mi < 4; mi++)
        #pragma unroll
        for (int ni = 0; ni < 8; ni++)
            #pragma unroll
            for (int r = 0; r < 4; r++) acc[mi][ni][r] = 0.f;

    g2_copy(sA[0], sB[0], A, B, brow, bcol, 0, Nd, Kd, tid);
    g2_copy(sA[1], sB[1], A, B, brow, bcol, BK, Nd, Kd, tid);

    int s = 0;
    for (int kt = 0; kt < KT; kt++) {
        asm volatile("cp.async.wait_group 1;");
        __syncthreads();
        if (kt + 2 < KT) {
            int s2 = s + 2; if (s2 >= 3) s2 -= 3;
            g2_copy(sA[s2], sB[s2], A, B, brow, bcol, (kt + 2) * BK, Nd, Kd, tid);
        }

        const float* Ac = sA[s];
        const float* Bc = sB[s];
        #pragma unroll
        for (int ks = 0; ks < 2; ks++) {
            int kc = ks * 8;
            uint32_t af[4][4], bf[8][2];
            #pragma unroll
            for (int mi = 0; mi < 4; mi++) {
                int rm = warp_m + mi * 16 + tg;
                af[mi][0] = __float_as_uint(Ac[(rm    ) * ASTRIDE + kc + tig]);
                af[mi][1] = __float_as_uint(Ac[(rm + 8) * ASTRIDE + kc + tig]);
                af[mi][2] = __float_as_uint(Ac[(rm    ) * ASTRIDE + kc + 4 + tig]);
                af[mi][3] = __float_as_uint(Ac[(rm + 8) * ASTRIDE + kc + 4 + tig]);
            }
            #pragma unroll
            for (int ni = 0; ni < 8; ni++) {
                int cn = warp_n + ni * 8 + tg;
                bf[ni][0] = __float_as_uint(Bc[(kc + tig    ) * BSTRIDE + cn]);
                bf[ni][1] = __float_as_uint(Bc[(kc + 4 + tig) * BSTRIDE + cn]);
            }
            #pragma unroll
            for (int mi = 0; mi < 4; mi++)
                #pragma unroll
                for (int ni = 0; ni < 8; ni++)
                    mma_tf32(acc[mi][ni], af[mi], bf[ni]);
        }
        __syncthreads();
        if (++s == 3) s = 0;
    }

    // Epilogue
    #pragma unroll
    for (int mi = 0; mi < 4; mi++) {
        int row0 = brow + warp_m + mi * 16 + tg;
        #pragma unroll
        for (int ni = 0; ni < 8; ni++) {
            int col = bcol + warp_n + ni * 8 + tig * 2;
            float2 bv = *(const float2*)(bias + col);
            #pragma unroll
            for (int half = 0; half < 2; half++) {
                int row = row0 + half * 8;
                float v0 = acc[mi][ni][half * 2 + 0] + bv.x;
                float v1 = acc[mi][ni][half * 2 + 1] + bv.y;
                if (epi == 1) { v0 = fmaxf(v0, 0.f); v1 = fmaxf(v1, 0.f); }
                if (epi == 2) {
                    float2 rv = *(const float2*)(res + (size_t)row * Nd + col);
                    v0 += rv.x; v1 += rv.y;
                }
                if (rnd) { v0 = rtf(v0); v1 = rtf(v1); }
                float2 o2; o2.x = v0; o2.y = v1;
                *(float2*)(C + (size_t)row * Nd + col) = o2;
            }
        }
    }
}

__global__ void __launch_bounds__(256, 1) gemm2(
    const float* __restrict__ A, const float* __restrict__ B,
    const float* __restrict__ bias, const float* __restrict__ res,
    float* __restrict__ C, int Nd, int Kd, int epi, int rnd)
{
    extern __shared__ float sm[];
    gemm2_core(A, B, bias, res, C, Nd, Kd,
               blockIdx.y * BM, blockIdx.x * BN, epi, rnd != 0, sm);
}

// Fused QKV: logical N = 3072; blockIdx.x in [0,12), nsel = x>>2.
__global__ void __launch_bounds__(256, 1) gemm2_qkv(
    const float* __restrict__ A,
    const float* __restrict__ Bq, const float* __restrict__ Bk,
    const float* __restrict__ Bv,
    const float* __restrict__ bq, const float* __restrict__ bk,
    const float* __restrict__ bv,
    float* __restrict__ Cq, float* __restrict__ Ck, float* __restrict__ Cv)
{
    extern __shared__ float sm[];
    int nsel = blockIdx.x >> 2;
    int bcol = (blockIdx.x & 3) * BN;
    const float* B  = (nsel == 0) ? Bq : (nsel == 1) ? Bk : Bv;
    const float* bi = (nsel == 0) ? bq : (nsel == 1) ? bk : bv;
    float* C        = (nsel == 0) ? Cq : (nsel == 1) ? Ck : Cv;
    // v is rounded here (consumed raw by attention MMA); q,k rounded in RoPE
    gemm2_core(A, B, bi, nullptr, C, DD, DD,
               blockIdx.y * BM, bcol, 0, nsel == 2, sm);
}

// ---------------------------------------------------------------------------
// RMSNorm (outputs tf32-rounded)
// ---------------------------------------------------------------------------
__global__ void __launch_bounds__(256) rmsnorm_kernel(
    const float* __restrict__ x, const float* __restrict__ g,
    float* __restrict__ out)
{
    int row = blockIdx.x;
    const float4* xr = (const float4*)(x + (size_t)row * DD);
    float4 xv = xr[threadIdx.x];
    float ss = xv.x * xv.x + xv.y * xv.y + xv.z * xv.z + xv.w * xv.w;
    #pragma unroll
    for (int off = 16; off > 0; off >>= 1)
        ss += __shfl_xor_sync(0xFFFFFFFFu, ss, off);
    __shared__ float sred[8];
    __shared__ float sscale;
    int warp = threadIdx.x >> 5;
    if ((threadIdx.x & 31) == 0) sred[warp] = ss;
    __syncthreads();
    if (threadIdx.x == 0) {
        float t = 0.f;
        #pragma unroll
        for (int i = 0; i < 8; i++) t += sred[i];
        sscale = rsqrtf(t / (float)DD + EPSF);
    }
    __syncthreads();
    float sc = sscale;
    float4 gv = ((const float4*)g)[threadIdx.x];
    float4 ov;
    ov.x = rtf(xv.x * sc * gv.x); ov.y = rtf(xv.y * sc * gv.y);
    ov.z = rtf(xv.z * sc * gv.z); ov.w = rtf(xv.w * sc * gv.w);
    ((float4*)(out + (size_t)row * DD))[threadIdx.x] = ov;
}

// ---------------------------------------------------------------------------
// RoPE (outputs tf32-rounded)
// ---------------------------------------------------------------------------
__global__ void rope_kernel(float* __restrict__ q, float* __restrict__ k)
{
    int idx = blockIdx.x * blockDim.x + threadIdx.x;
    int j   = idx & 31;
    int h   = (idx >> 5) & (HH - 1);
    int row = idx >> 9;
    int s   = row & (SS - 1);
    float inv_freq = powf(10000.f, -(float)(2 * j) / (float)DKK);
    float ang = (float)s * inv_freq;
    float sn, cs;
    sincosf(ang, &sn, &cs);
    size_t base = (size_t)row * DD + h * DKK + j;
    float q1 = q[base], q2 = q[base + 32];
    q[base]      = rtf(q1 * cs - q2 * sn);
    q[base + 32] = rtf(q2 * cs + q1 * sn);
    float k1 = k[base], k2 = k[base + 32];
    k[base]      = rtf(k1 * cs - k2 * sn);
    k[base + 32] = rtf(k2 * cs + k1 * sn);
}

// ---------------------------------------------------------------------------
// Flash attention with tf32 mma.sync (unchanged from R5)
// ---------------------------------------------------------------------------
#define KSS 68
#define VSS 72
#define PSS 68
#define OFF_K0 0
#define OFF_K1 (64 * KSS)
#define OFF_V0 (2 * 64 * KSS)
#define OFF_V1 (2 * 64 * KSS + 64 * VSS)
#define OFF_P  (2 * 64 * KSS + 2 * 64 * VSS)
#define ATTN_SMEM ((2 * 64 * KSS + 2 * 64 * VSS + 64 * PSS) * 4)

__global__ void __launch_bounds__(128, 2) attn_mma(
    const float* __restrict__ q, const float* __restrict__ k,
    const float* __restrict__ v, float* __restrict__ o)
{
    extern __shared__ float sm[];
    float* Ks[2] = { sm + OFF_K0, sm + OFF_K1 };
    float* Vs[2] = { sm + OFF_V0, sm + OFF_V1 };
    float* Ps    = sm + OFF_P;

    const int tid  = threadIdx.x;
    const int lane = tid & 31;
    const int wid  = tid >> 5;
    const int wm   = wid * 16;
    const int tg   = lane >> 2;
    const int tig  = lane & 3;

    const int h  = blockIdx.y;
    const int b  = blockIdx.z;
    const int q0 = blockIdx.x * 64;
    const size_t hb = (size_t)h * DKK;

    uint32_t qf[8][4];
    {
        size_t r0 = ((size_t)(b * SS + q0 + wm + tg)) * DD + hb;
        size_t r8 = r0 + (size_t)8 * DD;
        #pragma unroll
        for (int ks = 0; ks < 8; ks++) {
            int c = ks * 8 + tig;
            qf[ks][0] = __float_as_uint(q[r0 + c    ] * 0.125f);
            qf[ks][1] = __float_as_uint(q[r8 + c    ] * 0.125f);
            qf[ks][2] = __float_as_uint(q[r0 + c + 4] * 0.125f);
            qf[ks][3] = __float_as_uint(q[r8 + c + 4] * 0.125f);
        }
    }

    float oacc[8][4];
    #pragma unroll
    for (int ni = 0; ni < 8; ni++)
        #pragma unroll
        for (int r = 0; r < 4; r++) oacc[ni][r] = 0.f;
    float m0 = -1e30f, m1 = -1e30f, l0 = 0.f, l1 = 0.f;

    const size_t kvbase = ((size_t)(b * SS)) * DD + hb;

    #define KV_PREFETCH(bf, kt) do {                                          \
        const float* kg = k + kvbase + (size_t)((kt) * 64) * DD;              \
        const float* vg = v + kvbase + (size_t)((kt) * 64) * DD;              \
        uint32_t kb = smem_u32(Ks[bf]);                                       \
        uint32_t vb = smem_u32(Vs[bf]);                                       \
        _Pragma("unroll")                                                     \
        for (int i = 0; i < 8; i++) {                                         \
            int e = tid + i * 128;                                            \
            int row = e >> 4, c = e & 15;                                     \
            cp16(kb + row * (KSS * 4) + c * 16, kg + (size_t)row * DD + c * 4);\
            cp16(vb + row * (VSS * 4) + c * 16, vg + (size_t)row * DD + c * 4);\
        }                                                                     \
        asm volatile("cp.async.commit_group;");                               \
    } while (0)

    KV_PREFETCH(0, 0);

    const int NT = SS / 64;
    for (int kt = 0; kt < NT; kt++) {
        int cur = kt & 1;
        asm volatile("cp.async.wait_group 0;");
        __syncthreads();
        if (kt + 1 < NT) KV_PREFETCH(cur ^ 1, kt + 1);

        float sacc[8][4];
        #pragma unroll
        for (int ni = 0; ni < 8; ni++)
            #pragma unroll
            for (int r = 0; r < 4; r++) sacc[ni][r] = 0.f;

        const float* Kc = Ks[cur];
        #pragma unroll
        for (int ks = 0; ks < 8; ks++) {
            int kc = ks * 8;
            #pragma unroll
            for (int ni = 0; ni < 8; ni++) {
                uint32_t bf2[2];
                int cn = ni * 8 + tg;
                bf2[0] = __float_as_uint(Kc[cn * KSS + kc + tig]);
                bf2[1] = __float_as_uint(Kc[cn * KSS + kc + 4 + tig]);
                mma_tf32(sacc[ni], qf[ks], bf2);
            }
        }

        float rmax0 = -1e30f, rmax1 = -1e30f;
        #pragma unroll
        for (int ni = 0; ni < 8; ni++) {
            rmax0 = fmaxf(rmax0, fmaxf(sacc[ni][0], sacc[ni][1]));
            rmax1 = fmaxf(rmax1, fmaxf(sacc[ni][2], sacc[ni][3]));
        }
        #pragma unroll
        for (int d = 1; d < 4; d <<= 1) {
            rmax0 = fmaxf(rmax0, __shfl_xor_sync(0xFFFFFFFFu, rmax0, d));
            rmax1 = fmaxf(rmax1, __shfl_xor_sync(0xFFFFFFFFu, rmax1, d));
        }
        float nm0 = fmaxf(m0, rmax0);
        float nm1 = fmaxf(m1, rmax1);
        float corr0 = __expf(m0 - nm0);
        float corr1 = __expf(m1 - nm1);

        float rsum0 = 0.f, rsum1 = 0.f;
        #pragma unroll
        for (int ni = 0; ni < 8; ni++) {
            float p0 = __expf(sacc[ni][0] - nm0);
            float p1 = __expf(sacc[ni][1] - nm0);
            float p2 = __expf(sacc[ni][2] - nm1);
            float p3 = __expf(sacc[ni][3] - nm1);
            rsum0 += p0 + p1;
            rsum1 += p2 + p3;
            float* pr0 = Ps + (wm + tg) * PSS + ni * 8 + 2 * tig;
            float* pr1 = Ps + (wm + tg + 8) * PSS + ni * 8 + 2 * tig;
            pr0[0] = p0; pr0[1] = p1;
            pr1[0] = p2; pr1[1] = p3;
        }
        #pragma unroll
        for (int d = 1; d < 4; d <<= 1) {
            rsum0 += __shfl_xor_sync(0xFFFFFFFFu, rsum0, d);
            rsum1 += __shfl_xor_sync(0xFFFFFFFFu, rsum1, d);
        }
        l0 = l0 * corr0 + rsum0;
        l1 = l1 * corr1 + rsum1;
        m0 = nm0; m1 = nm1;

        #pragma unroll
        for (int ni = 0; ni < 8; ni++) {
            oacc[ni][0] *= corr0; oacc[ni][1] *= corr0;
            oacc[ni][2] *= corr1; oacc[ni][3] *= corr1;
        }

        __syncwarp();

        const float* Vc = Vs[cur];
        #pragma unroll
        for (int ks = 0; ks < 8; ks++) {
            int kc = ks * 8;
            uint32_t af[4];
            af[0] = f2tf32(Ps[(wm + tg    ) * PSS + kc + tig]);
            af[1] = f2tf32(Ps[(wm + tg + 8) * PSS + kc + tig]);
            af[2] = f2tf32(Ps[(wm + tg    ) * PSS + kc + 4 + tig]);
            af[3] = f2tf32(Ps[(wm + tg + 8) * PSS + kc + 4 + tig]);
            #pragma unroll
            for (int ni = 0; ni < 8; ni++) {
                uint32_t bf2[2];
                int cn = ni * 8 + tg;
                bf2[0] = __float_as_uint(Vc[(kc + tig    ) * VSS + cn]);
                bf2[1] = __float_as_uint(Vc[(kc + 4 + tig) * VSS + cn]);
                mma_tf32(oacc[ni], af, bf2);
            }
        }
        __syncwarp();
    }

    float inv0 = 1.f / l0;
    float inv1 = 1.f / l1;
    size_t r0 = ((size_t)(b * SS + q0 + wm + tg)) * DD + hb;
    size_t r8 = r0 + (size_t)8 * DD;
    #pragma unroll
    for (int ni = 0; ni < 8; ni++) {
        int c = ni * 8 + 2 * tig;
        float2 o0; o0.x = rtf(oacc[ni][0] * inv0); o0.y = rtf(oacc[ni][1] * inv0);
        float2 o1; o1.x = rtf(oacc[ni][2] * inv1); o1.y = rtf(oacc[ni][3] * inv1);
        *(float2*)(o + r0 + c) = o0;
        *(float2*)(o + r8 + c) = o1;
    }
    #undef KV_PREFETCH
}

// ---------------------------------------------------------------------------
// Host orchestration
// ---------------------------------------------------------------------------
extern "C" void kernel_launch(void* const* d_in, const int* in_sizes, int n_in,
                              void* d_out, int out_size)
{
    (void)in_sizes; (void)n_in; (void)out_size;

    const float* x  = (const float*)d_in[0];
    const float* wq = (const float*)d_in[1];
    const float* bq = (const float*)d_in[2];
    const float* wk = (const float*)d_in[3];
    const float* bk = (const float*)d_in[4];
    const float* wv = (const float*)d_in[5];
    const float* bv = (const float*)d_in[6];
    const float* wo = (const float*)d_in[7];
    const float* bo = (const float*)d_in[8];
    const float* w1 = (const float*)d_in[9];
    const float* b1 = (const float*)d_in[10];
    const float* w2 = (const float*)d_in[11];
    const float* b2 = (const float*)d_in[12];
    const float* g1 = (const float*)d_in[13];
    const float* g2 = (const float*)d_in[14];
    float* out = (float*)d_out;

    float *ph, *pq, *pk, *pv, *po, *px2, *ph2, *pff;
    float *prwq, *prwk, *prwv, *prwo, *prw1, *prw2;
    cudaGetSymbolAddress((void**)&ph,  g_h);
    cudaGetSymbolAddress((void**)&pq,  g_q);
    cudaGetSymbolAddress((void**)&pk,  g_k);
    cudaGetSymbolAddress((void**)&pv,  g_v);
    cudaGetSymbolAddress((void**)&po,  g_o);
    cudaGetSymbolAddress((void**)&px2, g_x2);
    cudaGetSymbolAddress((void**)&ph2, g_h2);
    cudaGetSymbolAddress((void**)&pff, g_ff);
    cudaGetSymbolAddress((void**)&prwq, g_rwq);
    cudaGetSymbolAddress((void**)&prwk, g_rwk);
    cudaGetSymbolAddress((void**)&prwv, g_rwv);
    cudaGetSymbolAddress((void**)&prwo, g_rwo);
    cudaGetSymbolAddress((void**)&prw1, g_rw1);
    cudaGetSymbolAddress((void**)&prw2, g_rw2);

    cudaFuncSetAttribute(attn_mma,
        cudaFuncAttributeMaxDynamicSharedMemorySize, ATTN_SMEM);
    cudaFuncSetAttribute(gemm2,
        cudaFuncAttributeMaxDynamicSharedMemorySize, GEMM2_SMEM);
    cudaFuncSetAttribute(gemm2_qkv,
        cudaFuncAttributeMaxDynamicSharedMemorySize, GEMM2_SMEM);

    // 1) round all weights to tf32 in one pass
    round_all_kernel<<<ROUND_BLOCKS, 256>>>(
        wq, wk, wv, wo, w1, w2, prwq, prwk, prwv, prwo, prw1, prw2);

    // 2) h = rmsnorm(x, g1)  (tf32-rounded output)
    rmsnorm_kernel<<<MM, 256>>>(x, g1, ph);

    // 3) fused QKV projection
    gemm2_qkv<<<dim3(12, MM / BM), 256, GEMM2_SMEM>>>(
        ph, prwq, prwk, prwv, bq, bk, bv, pq, pk, pv);

    // 4) RoPE
    rope_kernel<<<(MM * HH * 32) / 256, 256>>>(pq, pk);

    // 5) attention
    attn_mma<<<dim3(SS / 64, HH, BB), 128, ATTN_SMEM>>>(pq, pk, pv, po);

    // 6) x2 = x + o @ wo + bo
    gemm2<<<dim3(DD / BN, MM / BM), 256, GEMM2_SMEM>>>(
        po, prwo, bo, x, px2, DD, DD, 2, 0);

    // 7) h2 = rmsnorm(x2, g2)
    rmsnorm_kernel<<<MM, 256>>>(px2, g2, ph2);

    // 8) ff = relu(h2 @ w1 + b1)  (tf32-rounded)
    gemm2<<<dim3(DFFF / BN, MM / BM), 256, GEMM2_SMEM>>>(
        ph2, prw1, b1, nullptr, pff, DFFF, DD, 1, 1);

    // 9) out = x2 + ff @ w2 + b2
    gemm2<<<dim3(DD / BN, MM / BM), 256, GEMM2_SMEM>>>(
        pff, prw2, b2, px2, out, DD, DFFF, 2, 0);
}

// round 7
// speedup vs baseline: 1.0472x; 1.0472x over previous
#include <cuda_runtime.h>
#include <cuda_bf16.h>
#include <cstdint>
#include <math.h>

// Problem constants
#define BB   2
#define SS   2048
#define DD   1024
#define HH   16
#define DKK  64
#define DFFF 4096
#define MM   (BB * SS)          // 4096 rows
#define EPSF 1.1920929e-07f

// ---------------------------------------------------------------------------
// Scratch (device globals — no cudaMalloc allowed)
// ---------------------------------------------------------------------------
__device__ float g_h  [MM * DD];
__device__ float g_q  [MM * DD];
__device__ float g_k  [MM * DD];
__device__ float g_v  [MM * DD];
__device__ float g_o  [MM * DD];
__device__ float g_x2 [MM * DD];
__device__ float g_h2 [MM * DD];
__device__ float g_ff [MM * DFFF];
// tf32-pre-rounded, TRANSPOSED weights  W^T[N][K]
__device__ float g_rwq[DD * DD];
__device__ float g_rwk[DD * DD];
__device__ float g_rwv[DD * DD];
__device__ float g_rwo[DD * DD];
__device__ float g_rw1[DFFF * DD];   // w1^T: [4096][1024]
__device__ float g_rw2[DD * DFFF];   // w2^T: [1024][4096]

// ---------------------------------------------------------------------------
// helpers
// ---------------------------------------------------------------------------
__device__ __forceinline__ uint32_t smem_u32(const void* p) {
    uint32_t a;
    asm("{ .reg .u64 t; cvta.to.shared.u64 t, %1; cvt.u32.u64 %0, t; }"
        : "=r"(a) : "l"(p));
    return a;
}
__device__ __forceinline__ void cp16(uint32_t saddr, const void* g) {
    asm volatile("cp.async.cg.shared.global [%0], [%1], 16;" :: "r"(saddr), "l"(g));
}
__device__ __forceinline__ uint32_t f2tf32(float f) {
    uint32_t r;
    asm("cvt.rna.tf32.f32 %0, %1;" : "=r"(r) : "f"(f));
    return r;
}
__device__ __forceinline__ float rtf(float f) {
    return __uint_as_float(f2tf32(f));
}
__device__ __forceinline__ void mma_tf32(
    float* c, const uint32_t* a, const uint32_t* b)
{
    asm volatile(
        "mma.sync.aligned.m16n8k8.row.col.f32.tf32.tf32.f32 "
        "{%0,%1,%2,%3}, {%4,%5,%6,%7}, {%8,%9}, {%0,%1,%2,%3};"
        : "+f"(c[0]), "+f"(c[1]), "+f"(c[2]), "+f"(c[3])
        : "r"(a[0]), "r"(a[1]), "r"(a[2]), "r"(a[3]), "r"(b[0]), "r"(b[1]));
}
#define LDSM_X4(r0, r1, r2, r3, addr)                                         \
    asm volatile("ldmatrix.sync.aligned.m8n8.x4.shared.b16 {%0,%1,%2,%3}, [%4];" \
        : "=r"(r0), "=r"(r1), "=r"(r2), "=r"(r3) : "r"(addr))

// ---------------------------------------------------------------------------
// Transpose + tf32-round: out[C][R] = rtf(in[R][C]^T). Block (32,8).
// ---------------------------------------------------------------------------
__global__ void transpose_rtf_kernel(const float* __restrict__ in,
                                     float* __restrict__ out, int R, int C)
{
    __shared__ float t[32][33];
    int c0 = blockIdx.x * 32, r0 = blockIdx.y * 32;
    int x = threadIdx.x, y = threadIdx.y;
    #pragma unroll
    for (int i = 0; i < 32; i += 8)
        t[y + i][x] = in[(size_t)(r0 + y + i) * C + c0 + x];
    __syncthreads();
    #pragma unroll
    for (int i = 0; i < 32; i += 8)
        out[(size_t)(c0 + y + i) * R + r0 + x] = rtf(t[x][y + i]);
}

// ---------------------------------------------------------------------------
// tf32 mma.sync GEMM with ldmatrix fragment loads.
// C[M,N] = A[M,K] @ Bt[N,K]^T + bias (+relu / +residual)
// A and Bt both [rows][K] row-major, tf32-pre-rounded.
// CTA tile 128x128, BK=16, 256 threads (8 warps, 2m x 4n, 64x32 warp tile).
// Double-buffered cp.async. Smem stride 20 floats (ldmatrix conflict-free).
// EPI: 0 = bias, 1 = bias+relu, 2 = bias+residual. RND: round output to tf32.
// ---------------------------------------------------------------------------
#define BM 128
#define BN 128
#define BK 16
#define TSTR 20    // smem row stride (floats) for both tiles

template<int EPI, bool RND>
__global__ void __launch_bounds__(256, 2) gemm_mma(
    const float* __restrict__ A, const float* __restrict__ Bt,
    const float* __restrict__ bias, const float* __restrict__ res,
    float* __restrict__ C, int Nd, int Kd)
{
    __shared__ float As[2][BM][TSTR];
    __shared__ float Bs[2][BN][TSTR];

    const int tid  = threadIdx.x;
    const int lane = tid & 31;
    const int wid  = tid >> 5;
    const int warp_m = (wid >> 2) * 64;
    const int warp_n = (wid & 3) * 32;
    const int brow = blockIdx.y * BM;
    const int bcol = blockIdx.x * BN;
    const int KT = Kd / BK;

    const int tg  = lane >> 2;
    const int tig = lane & 3;
    const int lrow = lane & 15;           // ldmatrix row within 16-row group
    const int lcol = (lane >> 4) << 2;    // ldmatrix col group: 0 or 4

    float acc[4][4][4];
    #pragma unroll
    for (int i = 0; i < 4; i++)
        #pragma unroll
        for (int j = 0; j < 4; j++)
            #pragma unroll
            for (int r = 0; r < 4; r++) acc[i][j][r] = 0.f;

    // A tile: 128 rows x 16 floats = 512 float4; B tile identical shape.
    #define COPY_STAGE(s, kt) do {                                             \
        int k0 = (kt) * BK;                                                    \
        _Pragma("unroll")                                                      \
        for (int i = 0; i < 2; i++) {                                          \
            int e = tid + i * 256;                                             \
            int m = e >> 2, c4 = (e & 3) << 2;                                 \
            cp16(smem_u32(&As[s][m][c4]),                                      \
                 A + (size_t)(brow + m) * Kd + k0 + c4);                       \
        }                                                                      \
        _Pragma("unroll")                                                      \
        for (int i = 0; i < 2; i++) {                                          \
            int e = tid + i * 256;                                             \
            int n = e >> 2, c4 = (e & 3) << 2;                                 \
            cp16(smem_u32(&Bs[s][n][c4]),                                      \
                 Bt + (size_t)(bcol + n) * Kd + k0 + c4);                      \
        }                                                                      \
        asm volatile("cp.async.commit_group;");                                \
    } while (0)

    COPY_STAGE(0, 0);

    for (int kt = 0; kt < KT; kt++) {
        int s = kt & 1;
        if (kt + 1 < KT) {
            COPY_STAGE(s ^ 1, kt + 1);
            asm volatile("cp.async.wait_group 1;");
        } else {
            asm volatile("cp.async.wait_group 0;");
        }
        __syncthreads();

        uint32_t aBase = smem_u32(&As[s][warp_m + lrow][lcol]);
        uint32_t bBase = smem_u32(&Bs[s][warp_n + lrow][lcol]);

        #pragma unroll
        for (int ks = 0; ks < 2; ks++) {
            const uint32_t kcb = ks * 8 * 4;
            uint32_t af[4][4], bf[4][2];
            #pragma unroll
            for (int mi = 0; mi < 4; mi++)
                LDSM_X4(af[mi][0], af[mi][1], af[mi][2], af[mi][3],
                        aBase + (uint32_t)(mi * 16 * TSTR * 4) + kcb);
            #pragma unroll
            for (int nj = 0; nj < 2; nj++) {
                uint32_t r0, r1, r2, r3;
                LDSM_X4(r0, r1, r2, r3,
                        bBase + (uint32_t)(nj * 16 * TSTR * 4) + kcb);
                bf[2 * nj][0] = r0; bf[2 * nj + 1][0] = r1;
                bf[2 * nj][1] = r2; bf[2 * nj + 1][1] = r3;
            }
            #pragma unroll
            for (int mi = 0; mi < 4; mi++)
                #pragma unroll
                for (int ni = 0; ni < 4; ni++)
                    mma_tf32(acc[mi][ni], af[mi], bf[ni]);
        }
        __syncthreads();
    }

    // Epilogue
    #pragma unroll
    for (int mi = 0; mi < 4; mi++) {
        int row0 = brow + warp_m + mi * 16 + tg;
        #pragma unroll
        for (int ni = 0; ni < 4; ni++) {
            int col = bcol + warp_n + ni * 8 + tig * 2;
            float2 bv = *(const float2*)(bias + col);
            #pragma unroll
            for (int half = 0; half < 2; half++) {
                int row = row0 + half * 8;
                float v0 = acc[mi][ni][half * 2 + 0] + bv.x;
                float v1 = acc[mi][ni][half * 2 + 1] + bv.y;
                if (EPI == 1) { v0 = fmaxf(v0, 0.f); v1 = fmaxf(v1, 0.f); }
                if (EPI == 2) {
                    float2 rv = *(const float2*)(res + (size_t)row * Nd + col);
                    v0 += rv.x; v1 += rv.y;
                }
                if (RND) { v0 = rtf(v0); v1 = rtf(v1); }
                float2 o2; o2.x = v0; o2.y = v1;
                *(float2*)(C + (size_t)row * Nd + col) = o2;
            }
        }
    }
    #undef COPY_STAGE
}

// ---------------------------------------------------------------------------
// RMSNorm (outputs tf32-rounded)
// ---------------------------------------------------------------------------
__global__ void __launch_bounds__(256) rmsnorm_kernel(
    const float* __restrict__ x, const float* __restrict__ g,
    float* __restrict__ out)
{
    int row = blockIdx.x;
    const float4* xr = (const float4*)(x + (size_t)row * DD);
    float4 xv = xr[threadIdx.x];
    float ss = xv.x * xv.x + xv.y * xv.y + xv.z * xv.z + xv.w * xv.w;
    #pragma unroll
    for (int off = 16; off > 0; off >>= 1)
        ss += __shfl_xor_sync(0xFFFFFFFFu, ss, off);
    __shared__ float sred[8];
    __shared__ float sscale;
    int warp = threadIdx.x >> 5;
    if ((threadIdx.x & 31) == 0) sred[warp] = ss;
    __syncthreads();
    if (threadIdx.x == 0) {
        float t = 0.f;
        #pragma unroll
        for (int i = 0; i < 8; i++) t += sred[i];
        sscale = rsqrtf(t / (float)DD + EPSF);
    }
    __syncthreads();
    float sc = sscale;
    float4 gv = ((const float4*)g)[threadIdx.x];
    float4 ov;
    ov.x = rtf(xv.x * sc * gv.x); ov.y = rtf(xv.y * sc * gv.y);
    ov.z = rtf(xv.z * sc * gv.z); ov.w = rtf(xv.w * sc * gv.w);
    ((float4*)(out + (size_t)row * DD))[threadIdx.x] = ov;
}

// ---------------------------------------------------------------------------
// RoPE (outputs tf32-rounded)
// ---------------------------------------------------------------------------
__global__ void rope_kernel(float* __restrict__ q, float* __restrict__ k)
{
    int idx = blockIdx.x * blockDim.x + threadIdx.x;
    int j   = idx & 31;
    int h   = (idx >> 5) & (HH - 1);
    int row = idx >> 9;
    int s   = row & (SS - 1);
    float inv_freq = powf(10000.f, -(float)(2 * j) / (float)DKK);
    float ang = (float)s * inv_freq;
    float sn, cs;
    sincosf(ang, &sn, &cs);
    size_t base = (size_t)row * DD + h * DKK + j;
    float q1 = q[base], q2 = q[base + 32];
    q[base]      = rtf(q1 * cs - q2 * sn);
    q[base + 32] = rtf(q2 * cs + q1 * sn);
    float k1 = k[base], k2 = k[base + 32];
    k[base]      = rtf(k1 * cs - k2 * sn);
    k[base + 32] = rtf(k2 * cs + k1 * sn);
}

// ---------------------------------------------------------------------------
// Flash attention with tf32 mma.sync; K fragments via ldmatrix.
// CTA: 64 queries x one (b,h). 4 warps. K/V 64x64 double-buffered cp.async.
// ---------------------------------------------------------------------------
#define KSS 68
#define VSS 72
#define PSS 68
#define OFF_K0 0
#define OFF_K1 (64 * KSS)
#define OFF_V0 (2 * 64 * KSS)
#define OFF_V1 (2 * 64 * KSS + 64 * VSS)
#define OFF_P  (2 * 64 * KSS + 2 * 64 * VSS)
#define ATTN_SMEM ((2 * 64 * KSS + 2 * 64 * VSS + 64 * PSS) * 4)

__global__ void __launch_bounds__(128, 2) attn_mma(
    const float* __restrict__ q, const float* __restrict__ k,
    const float* __restrict__ v, float* __restrict__ o)
{
    extern __shared__ float sm[];
    float* Ks[2] = { sm + OFF_K0, sm + OFF_K1 };
    float* Vs[2] = { sm + OFF_V0, sm + OFF_V1 };
    float* Ps    = sm + OFF_P;

    const int tid  = threadIdx.x;
    const int lane = tid & 31;
    const int wid  = tid >> 5;
    const int wm   = wid * 16;
    const int tg   = lane >> 2;
    const int tig  = lane & 3;
    const int lrow = lane & 15;
    const int lcol = (lane >> 4) << 2;

    const int h  = blockIdx.y;
    const int b  = blockIdx.z;
    const int q0 = blockIdx.x * 64;
    const size_t hb = (size_t)h * DKK;

    uint32_t qf[8][4];
    {
        size_t r0 = ((size_t)(b * SS + q0 + wm + tg)) * DD + hb;
        size_t r8 = r0 + (size_t)8 * DD;
        #pragma unroll
        for (int ks = 0; ks < 8; ks++) {
            int c = ks * 8 + tig;
            qf[ks][0] = __float_as_uint(q[r0 + c    ] * 0.125f);
            qf[ks][1] = __float_as_uint(q[r8 + c    ] * 0.125f);
            qf[ks][2] = __float_as_uint(q[r0 + c + 4] * 0.125f);
            qf[ks][3] = __float_as_uint(q[r8 + c + 4] * 0.125f);
        }
    }

    float oacc[8][4];
    #pragma unroll
    for (int ni = 0; ni < 8; ni++)
        #pragma unroll
        for (int r = 0; r < 4; r++) oacc[ni][r] = 0.f;
    float m0 = -1e30f, m1 = -1e30f, l0 = 0.f, l1 = 0.f;

    const size_t kvbase = ((size_t)(b * SS)) * DD + hb;

    #define KV_PREFETCH(bf, kt) do {                                          \
        const float* kg = k + kvbase + (size_t)((kt) * 64) * DD;              \
        const float* vg = v + kvbase + (size_t)((kt) * 64) * DD;              \
        uint32_t kb = smem_u32(Ks[bf]);                                       \
        uint32_t vb = smem_u32(Vs[bf]);                                       \
        _Pragma("unroll")                                                     \
        for (int i = 0; i < 8; i++) {                                         \
            int e = tid + i * 128;                                            \
            int row = e >> 4, c = e & 15;                                     \
            cp16(kb + row * (KSS * 4) + c * 16, kg + (size_t)row * DD + c * 4);\
            cp16(vb + row * (VSS * 4) + c * 16, vg + (size_t)row * DD + c * 4);\
        }                                                                     \
        asm volatile("cp.async.commit_group;");                               \
    } while (0)

    KV_PREFETCH(0, 0);

    const int NT = SS / 64;
    for (int kt = 0; kt < NT; kt++) {
        int cur = kt & 1;
        asm volatile("cp.async.wait_group 0;");
        __syncthreads();
        if (kt + 1 < NT) KV_PREFETCH(cur ^ 1, kt + 1);

        // S = Q @ K^T  (K fragments via ldmatrix)
        float sacc[8][4];
        #pragma unroll
        for (int ni = 0; ni < 8; ni++)
            #pragma unroll
            for (int r = 0; r < 4; r++) sacc[ni][r] = 0.f;

        uint32_t kBase = smem_u32(Ks[cur] + lrow * KSS + lcol);
        #pragma unroll
        for (int ks = 0; ks < 8; ks++) {
            const uint32_t kcb = ks * 8 * 4;
            #pragma unroll
            for (int nj = 0; nj < 4; nj++) {
                uint32_t r0, r1, r2, r3;
                LDSM_X4(r0, r1, r2, r3,
                        kBase + (uint32_t)(nj * 16 * KSS * 4) + kcb);
                uint32_t b0[2] = { r0, r2 };
                uint32_t b1[2] = { r1, r3 };
                mma_tf32(sacc[2 * nj    ], qf[ks], b0);
                mma_tf32(sacc[2 * nj + 1], qf[ks], b1);
            }
        }

        // online softmax
        float rmax0 = -1e30f, rmax1 = -1e30f;
        #pragma unroll
        for (int ni = 0; ni < 8; ni++) {
            rmax0 = fmaxf(rmax0, fmaxf(sacc[ni][0], sacc[ni][1]));
            rmax1 = fmaxf(rmax1, fmaxf(sacc[ni][2], sacc[ni][3]));
        }
        #pragma unroll
        for (int d = 1; d < 4; d <<= 1) {
            rmax0 = fmaxf(rmax0, __shfl_xor_sync(0xFFFFFFFFu, rmax0, d));
            rmax1 = fmaxf(rmax1, __shfl_xor_sync(0xFFFFFFFFu, rmax1, d));
        }
        float nm0 = fmaxf(m0, rmax0);
        float nm1 = fmaxf(m1, rmax1);
        float corr0 = __expf(m0 - nm0);
        float corr1 = __expf(m1 - nm1);

        float rsum0 = 0.f, rsum1 = 0.f;
        #pragma unroll
        for (int ni = 0; ni < 8; ni++) {
            float p0 = __expf(sacc[ni][0] - nm0);
            float p1 = __expf(sacc[ni][1] - nm0);
            float p2 = __expf(sacc[ni][2] - nm1);
            float p3 = __expf(sacc[ni][3] - nm1);
            rsum0 += p0 + p1;
            rsum1 += p2 + p3;
            float* pr0 = Ps + (wm + tg) * PSS + ni * 8 + 2 * tig;
            float* pr1 = Ps + (wm + tg + 8) * PSS + ni * 8 + 2 * tig;
            pr0[0] = p0; pr0[1] = p1;
            pr1[0] = p2; pr1[1] = p3;
        }
        #pragma unroll
        for (int d = 1; d < 4; d <<= 1) {
            rsum0 += __shfl_xor_sync(0xFFFFFFFFu, rsum0, d);
            rsum1 += __shfl_xor_sync(0xFFFFFFFFu, rsum1, d);
        }
        l0 = l0 * corr0 + rsum0;
        l1 = l1 * corr1 + rsum1;
        m0 = nm0; m1 = nm1;

        #pragma unroll
        for (int ni = 0; ni < 8; ni++) {
            oacc[ni][0] *= corr0; oacc[ni][1] *= corr0;
            oacc[ni][2] *= corr1; oacc[ni][3] *= corr1;
        }

        __syncwarp();

        // O += P @ V
        const float* Vc = Vs[cur];
        #pragma unroll
        for (int ks = 0; ks < 8; ks++) {
            int kc = ks * 8;
            uint32_t af[4];
            af[0] = f2tf32(Ps[(wm + tg    ) * PSS + kc + tig]);
            af[1] = f2tf32(Ps[(wm + tg + 8) * PSS + kc + tig]);
            af[2] = f2tf32(Ps[(wm + tg    ) * PSS + kc + 4 + tig]);
            af[3] = f2tf32(Ps[(wm + tg + 8) * PSS + kc + 4 + tig]);
            #pragma unroll
            for (int ni = 0; ni < 8; ni++) {
                uint32_t bf2[2];
                int cn = ni * 8 + tg;
                bf2[0] = __float_as_uint(Vc[(kc + tig    ) * VSS + cn]);
                bf2[1] = __float_as_uint(Vc[(kc + 4 + tig) * VSS + cn]);
                mma_tf32(oacc[ni], af, bf2);
            }
        }
        __syncwarp();
    }

    float inv0 = 1.f / l0;
    float inv1 = 1.f / l1;
    size_t r0 = ((size_t)(b * SS + q0 + wm + tg)) * DD + hb;
    size_t r8 = r0 + (size_t)8 * DD;
    #pragma unroll
    for (int ni = 0; ni < 8; ni++) {
        int c = ni * 8 + 2 * tig;
        float2 o0; o0.x = rtf(oacc[ni][0] * inv0); o0.y = rtf(oacc[ni][1] * inv0);
        float2 o1; o1.x = rtf(oacc[ni][2] * inv1); o1.y = rtf(oacc[ni][3] * inv1);
        *(float2*)(o + r0 + c) = o0;
        *(float2*)(o + r8 + c) = o1;
    }
    #undef KV_PREFETCH
}

// ---------------------------------------------------------------------------
// Host orchestration
// ---------------------------------------------------------------------------
extern "C" void kernel_launch(void* const* d_in, const int* in_sizes, int n_in,
                              void* d_out, int out_size)
{
    (void)in_sizes; (void)n_in; (void)out_size;

    const float* x  = (const float*)d_in[0];
    const float* wq = (const float*)d_in[1];
    const float* bq = (const float*)d_in[2];
    const float* wk = (const float*)d_in[3];
    const float* bk = (const float*)d_in[4];
    const float* wv = (const float*)d_in[5];
    const float* bv = (const float*)d_in[6];
    const float* wo = (const float*)d_in[7];
    const float* bo = (const float*)d_in[8];
    const float* w1 = (const float*)d_in[9];
    const float* b1 = (const float*)d_in[10];
    const float* w2 = (const float*)d_in[11];
    const float* b2 = (const float*)d_in[12];
    const float* g1 = (const float*)d_in[13];
    const float* g2 = (const float*)d_in[14];
    float* out = (float*)d_out;

    float *ph, *pq, *pk, *pv, *po, *px2, *ph2, *pff;
    float *prwq, *prwk, *prwv, *prwo, *prw1, *prw2;
    cudaGetSymbolAddress((void**)&ph,  g_h);
    cudaGetSymbolAddress((void**)&pq,  g_q);
    cudaGetSymbolAddress((void**)&pk,  g_k);
    cudaGetSymbolAddress((void**)&pv,  g_v);
    cudaGetSymbolAddress((void**)&po,  g_o);
    cudaGetSymbolAddress((void**)&px2, g_x2);
    cudaGetSymbolAddress((void**)&ph2, g_h2);
    cudaGetSymbolAddress((void**)&pff, g_ff);
    cudaGetSymbolAddress((void**)&prwq, g_rwq);
    cudaGetSymbolAddress((void**)&prwk, g_rwk);
    cudaGetSymbolAddress((void**)&prwv, g_rwv);
    cudaGetSymbolAddress((void**)&prwo, g_rwo);
    cudaGetSymbolAddress((void**)&prw1, g_rw1);
    cudaGetSymbolAddress((void**)&prw2, g_rw2);

    cudaFuncSetAttribute(attn_mma,
        cudaFuncAttributeMaxDynamicSharedMemorySize, ATTN_SMEM);

    dim3 gD(DD / BN,   MM / BM);   // (8, 32)
    dim3 gF(DFFF / BN, MM / BM);   // (32, 32)
    dim3 tb(32, 8);

    // 1) transpose + tf32-round all weights:  W[K,N] -> W^T[N,K]
    transpose_rtf_kernel<<<dim3(DD / 32, DD / 32), tb>>>(wq, prwq, DD, DD);
    transpose_rtf_kernel<<<dim3(DD / 32, DD / 32), tb>>>(wk, prwk, DD, DD);
    transpose_rtf_kernel<<<dim3(DD / 32, DD / 32), tb>>>(wv, prwv, DD, DD);
    transpose_rtf_kernel<<<dim3(DD / 32, DD / 32), tb>>>(wo, prwo, DD, DD);
    transpose_rtf_kernel<<<dim3(DFFF / 32, DD / 32), tb>>>(w1, prw1, DD, DFFF);
    transpose_rtf_kernel<<<dim3(DD / 32, DFFF / 32), tb>>>(w2, prw2, DFFF, DD);

    // 2) h = rmsnorm(x, g1)  (tf32-rounded output)
    rmsnorm_kernel<<<MM, 256>>>(x, g1, ph);

    // 3) QKV projections
    gemm_mma<0, false><<<gD, 256>>>(ph, prwq, bq, nullptr, pq, DD, DD);
    gemm_mma<0, false><<<gD, 256>>>(ph, prwk, bk, nullptr, pk, DD, DD);
    gemm_mma<0, true ><<<gD, 256>>>(ph, prwv, bv, nullptr, pv, DD, DD);

    // 4) RoPE
    rope_kernel<<<(MM * HH * 32) / 256, 256>>>(pq, pk);

    // 5) attention
    attn_mma<<<dim3(SS / 64, HH, BB), 128, ATTN_SMEM>>>(pq, pk, pv, po);

    // 6) x2 = x + o @ wo + bo
    gemm_mma<2, false><<<gD, 256>>>(po, prwo, bo, x, px2, DD, DD);

    // 7) h2 = rmsnorm(x2, g2)
    rmsnorm_kernel<<<MM, 256>>>(px2, g2, ph2);

    // 8) ff = relu(h2 @ w1 + b1)  (tf32-rounded)
    gemm_mma<1, true ><<<gF, 256>>>(ph2, prw1, b1, nullptr, pff, DFFF, DD);

    // 9) out = x2 + ff @ w2 + b2
    gemm_mma<2, false><<<gD, 256>>>(pff, prw2, b2, px2, out, DD, DFFF);
}

// round 8
// speedup vs baseline: 1.1432x; 1.0917x over previous
#include <cuda_runtime.h>
#include <cuda_bf16.h>
#include <cstdint>
#include <math.h>

// Problem constants
#define BB   2
#define SS   2048
#define DD   1024
#define HH   16
#define DKK  64
#define DFFF 4096
#define MM   (BB * SS)          // 4096 rows
#define EPSF 1.1920929e-07f

// ---------------------------------------------------------------------------
// Scratch (device globals — no cudaMalloc allowed)
// ---------------------------------------------------------------------------
__device__ float g_h  [MM * DD];
__device__ float g_q  [MM * DD];
__device__ float g_k  [MM * DD];
__device__ float g_v  [MM * DD];
__device__ float g_o  [MM * DD];
__device__ float g_x2 [MM * DD];
__device__ float g_h2 [MM * DD];
__device__ float g_ff [MM * DFFF];
// tf32-pre-rounded weights (original [K,N] layout)
__device__ float g_rwq[DD * DD];
__device__ float g_rwk[DD * DD];
__device__ float g_rwv[DD * DD];
__device__ float g_rwo[DD * DD];
__device__ float g_rw1[DD * DFFF];
__device__ float g_rw2[DFFF * DD];

// ---------------------------------------------------------------------------
// helpers
// ---------------------------------------------------------------------------
__device__ __forceinline__ uint32_t smem_u32(const void* p) {
    uint32_t a;
    asm("{ .reg .u64 t; cvta.to.shared.u64 t, %1; cvt.u32.u64 %0, t; }"
        : "=r"(a) : "l"(p));
    return a;
}
__device__ __forceinline__ void cp16(uint32_t saddr, const void* g) {
    asm volatile("cp.async.cg.shared.global [%0], [%1], 16;" :: "r"(saddr), "l"(g));
}
__device__ __forceinline__ uint32_t f2tf32(float f) {
    uint32_t r;
    asm("cvt.rna.tf32.f32 %0, %1;" : "=r"(r) : "f"(f));
    return r;
}
__device__ __forceinline__ float rtf(float f) {
    return __uint_as_float(f2tf32(f));
}
__device__ __forceinline__ void mma_tf32(
    float* c, const uint32_t* a, const uint32_t* b)
{
    asm volatile(
        "mma.sync.aligned.m16n8k8.row.col.f32.tf32.tf32.f32 "
        "{%0,%1,%2,%3}, {%4,%5,%6,%7}, {%8,%9}, {%0,%1,%2,%3};"
        : "+f"(c[0]), "+f"(c[1]), "+f"(c[2]), "+f"(c[3])
        : "r"(a[0]), "r"(a[1]), "r"(a[2]), "r"(a[3]), "r"(b[0]), "r"(b[1]));
}

// ---------------------------------------------------------------------------
// Fused tf32 rounding for all 6 weights in one launch.
// ---------------------------------------------------------------------------
#define SEG  262144                 // (DD*DD)/4
#define SEGF 1048576                // (DD*DFFF)/4
__global__ void __launch_bounds__(256) round_all_kernel(
    const float* __restrict__ s0, const float* __restrict__ s1,
    const float* __restrict__ s2, const float* __restrict__ s3,
    const float* __restrict__ s4, const float* __restrict__ s5,
    float* __restrict__ d0, float* __restrict__ d1,
    float* __restrict__ d2, float* __restrict__ d3,
    float* __restrict__ d4, float* __restrict__ d5)
{
    long long i = (long long)blockIdx.x * 256 + threadIdx.x;
    const float4* src;
    float4* dst;
    long long off;
    if      (i < 1 * SEG) { src = (const float4*)s0; dst = (float4*)d0; off = i; }
    else if (i < 2 * SEG) { src = (const float4*)s1; dst = (float4*)d1; off = i - 1 * SEG; }
    else if (i < 3 * SEG) { src = (const float4*)s2; dst = (float4*)d2; off = i - 2 * SEG; }
    else if (i < 4 * SEG) { src = (const float4*)s3; dst = (float4*)d3; off = i - 3 * SEG; }
    else if (i < 4 * SEG + SEGF) { src = (const float4*)s4; dst = (float4*)d4; off = i - 4 * SEG; }
    else                   { src = (const float4*)s5; dst = (float4*)d5; off = i - 4 * SEG - SEGF; }
    float4 v = src[off];
    v.x = rtf(v.x); v.y = rtf(v.y); v.z = rtf(v.z); v.w = rtf(v.w);
    dst[off] = v;
}
#define ROUND_BLOCKS ((4 * SEG + 2 * SEGF) / 256)

// ---------------------------------------------------------------------------
// tf32 mma.sync GEMM — exact R5 configuration (proven).
// C[M,N] = A[M,K] @ B[K,N] + bias (+relu / +residual)
// CTA 128x128, BK=16, 256 threads (2x4 warps, 64x32 warp tile),
// double-buffered cp.async, 2 CTAs/SM.
// epi: 0 = bias, 1 = bias+relu, 2 = bias+residual. rnd: round output to tf32.
// ---------------------------------------------------------------------------
#define BM 128
#define BN 128
#define BK 16
#define APAD 20
#define BPAD 136

__device__ __forceinline__ void gemm_core(
    const float* __restrict__ A, const float* __restrict__ Bm,
    const float* __restrict__ bias, const float* __restrict__ res,
    float* __restrict__ C, int Nd, int Kd, int brow, int bcol,
    int epi, bool rnd,
    float (*As)[BM][APAD], float (*Bs)[BK][BPAD])
{
    const int tid  = threadIdx.x;
    const int lane = tid & 31;
    const int wid  = tid >> 5;
    const int warp_m = (wid >> 2) * 64;
    const int warp_n = (wid & 3) * 32;
    const int KT = Kd / BK;

    const int tg  = lane >> 2;
    const int tig = lane & 3;

    float acc[4][4][4];
    #pragma unroll
    for (int i = 0; i < 4; i++)
        #pragma unroll
        for (int j = 0; j < 4; j++)
            #pragma unroll
            for (int r = 0; r < 4; r++) acc[i][j][r] = 0.f;

    #define COPY_STAGE(s, kt) do {                                             \
        int k0 = (kt) * BK;                                                    \
        _Pragma("unroll")                                                      \
        for (int i = 0; i < 2; i++) {                                          \
            int e = tid + i * 256;                                             \
            int m = e >> 2, c4 = (e & 3) << 2;                                 \
            cp16(smem_u32(&As[s][m][c4]),                                      \
                 A + (size_t)(brow + m) * Kd + k0 + c4);                       \
        }                                                                      \
        _Pragma("unroll")                                                      \
        for (int i = 0; i < 2; i++) {                                          \
            int e = tid + i * 256;                                             \
            int kr = e >> 5, c4 = (e & 31) << 2;                               \
            cp16(smem_u32(&Bs[s][kr][c4]),                                     \
                 Bm + (size_t)(k0 + kr) * Nd + bcol + c4);                     \
        }                                                                      \
        asm volatile("cp.async.commit_group;");                                \
    } while (0)

    COPY_STAGE(0, 0);

    for (int kt = 0; kt < KT; kt++) {
        int s = kt & 1;
        if (kt + 1 < KT) {
            COPY_STAGE(s ^ 1, kt + 1);
            asm volatile("cp.async.wait_group 1;");
        } else {
            asm volatile("cp.async.wait_group 0;");
        }
        __syncthreads();

        #pragma unroll
        for (int ks = 0; ks < 2; ks++) {
            int kc = ks * 8;
            uint32_t af[4][4], bf[4][2];
            #pragma unroll
            for (int mi = 0; mi < 4; mi++) {
                int rm = warp_m + mi * 16 + tg;
                af[mi][0] = __float_as_uint(As[s][rm    ][kc + tig]);
                af[mi][1] = __float_as_uint(As[s][rm + 8][kc + tig]);
                af[mi][2] = __float_as_uint(As[s][rm    ][kc + 4 + tig]);
                af[mi][3] = __float_as_uint(As[s][rm + 8][kc + 4 + tig]);
            }
            #pragma unroll
            for (int ni = 0; ni < 4; ni++) {
                int cn = warp_n + ni * 8 + tg;
                bf[ni][0] = __float_as_uint(Bs[s][kc + tig    ][cn]);
                bf[ni][1] = __float_as_uint(Bs[s][kc + 4 + tig][cn]);
            }
            #pragma unroll
            for (int mi = 0; mi < 4; mi++)
                #pragma unroll
                for (int ni = 0; ni < 4; ni++)
                    mma_tf32(acc[mi][ni], af[mi], bf[ni]);
        }
        __syncthreads();
    }

    #pragma unroll
    for (int mi = 0; mi < 4; mi++) {
        int row0 = brow + warp_m + mi * 16 + tg;
        #pragma unroll
        for (int ni = 0; ni < 4; ni++) {
            int col = bcol + warp_n + ni * 8 + tig * 2;
            float2 bv = *(const float2*)(bias + col);
            #pragma unroll
            for (int half = 0; half < 2; half++) {
                int row = row0 + half * 8;
                float v0 = acc[mi][ni][half * 2 + 0] + bv.x;
                float v1 = acc[mi][ni][half * 2 + 1] + bv.y;
                if (epi == 1) { v0 = fmaxf(v0, 0.f); v1 = fmaxf(v1, 0.f); }
                if (epi == 2) {
                    float2 rv = *(const float2*)(res + (size_t)row * Nd + col);
                    v0 += rv.x; v1 += rv.y;
                }
                if (rnd) { v0 = rtf(v0); v1 = rtf(v1); }
                float2 o2; o2.x = v0; o2.y = v1;
                *(float2*)(C + (size_t)row * Nd + col) = o2;
            }
        }
    }
    #undef COPY_STAGE
}

__global__ void __launch_bounds__(256, 2) gemm_mma(
    const float* __restrict__ A, const float* __restrict__ Bm,
    const float* __restrict__ bias, const float* __restrict__ res,
    float* __restrict__ C, int Nd, int Kd, int epi, int rnd)
{
    __shared__ float As[2][BM][APAD];
    __shared__ float Bs[2][BK][BPAD];
    gemm_core(A, Bm, bias, res, C, Nd, Kd,
              blockIdx.y * BM, blockIdx.x * BN, epi, rnd != 0, As, Bs);
}

// Fused QKV: grid.x in [0,24); nsel = x>>3 picks (wq,wk,wv).
__global__ void __launch_bounds__(256, 2) gemm_qkv(
    const float* __restrict__ A,
    const float* __restrict__ Bq, const float* __restrict__ Bk,
    const float* __restrict__ Bv,
    const float* __restrict__ bq, const float* __restrict__ bk,
    const float* __restrict__ bv,
    float* __restrict__ Cq, float* __restrict__ Ck, float* __restrict__ Cv)
{
    __shared__ float As[2][BM][APAD];
    __shared__ float Bs[2][BK][BPAD];
    int nsel = blockIdx.x >> 3;
    int bcol = (blockIdx.x & 7) * BN;
    const float* B  = (nsel == 0) ? Bq : (nsel == 1) ? Bk : Bv;
    const float* bi = (nsel == 0) ? bq : (nsel == 1) ? bk : bv;
    float* C        = (nsel == 0) ? Cq : (nsel == 1) ? Ck : Cv;
    // v rounds here (raw consumption by attention MMA); q,k round in RoPE
    gemm_core(A, B, bi, nullptr, C, DD, DD,
              blockIdx.y * BM, bcol, 0, nsel == 2, As, Bs);
}

// ---------------------------------------------------------------------------
// RMSNorm (outputs tf32-rounded)
// ---------------------------------------------------------------------------
__global__ void __launch_bounds__(256) rmsnorm_kernel(
    const float* __restrict__ x, const float* __restrict__ g,
    float* __restrict__ out)
{
    int row = blockIdx.x;
    const float4* xr = (const float4*)(x + (size_t)row * DD);
    float4 xv = xr[threadIdx.x];
    float ss = xv.x * xv.x + xv.y * xv.y + xv.z * xv.z + xv.w * xv.w;
    #pragma unroll
    for (int off = 16; off > 0; off >>= 1)
        ss += __shfl_xor_sync(0xFFFFFFFFu, ss, off);
    __shared__ float sred[8];
    __shared__ float sscale;
    int warp = threadIdx.x >> 5;
    if ((threadIdx.x & 31) == 0) sred[warp] = ss;
    __syncthreads();
    if (threadIdx.x == 0) {
        float t = 0.f;
        #pragma unroll
        for (int i = 0; i < 8; i++) t += sred[i];
        sscale = rsqrtf(t / (float)DD + EPSF);
    }
    __syncthreads();
    float sc = sscale;
    float4 gv = ((const float4*)g)[threadIdx.x];
    float4 ov;
    ov.x = rtf(xv.x * sc * gv.x); ov.y = rtf(xv.y * sc * gv.y);
    ov.z = rtf(xv.z * sc * gv.z); ov.w = rtf(xv.w * sc * gv.w);
    ((float4*)(out + (size_t)row * DD))[threadIdx.x] = ov;
}

// ---------------------------------------------------------------------------
// RoPE (outputs tf32-rounded)
// ---------------------------------------------------------------------------
__global__ void rope_kernel(float* __restrict__ q, float* __restrict__ k)
{
    int idx = blockIdx.x * blockDim.x + threadIdx.x;
    int j   = idx & 31;
    int h   = (idx >> 5) & (HH - 1);
    int row = idx >> 9;
    int s   = row & (SS - 1);
    float inv_freq = powf(10000.f, -(float)(2 * j) / (float)DKK);
    float ang = (float)s * inv_freq;
    float sn, cs;
    sincosf(ang, &sn, &cs);
    size_t base = (size_t)row * DD + h * DKK + j;
    float q1 = q[base], q2 = q[base + 32];
    q[base]      = rtf(q1 * cs - q2 * sn);
    q[base + 32] = rtf(q2 * cs + q1 * sn);
    float k1 = k[base], k2 = k[base + 32];
    k[base]      = rtf(k1 * cs - k2 * sn);
    k[base + 32] = rtf(k2 * cs + k1 * sn);
}

// ---------------------------------------------------------------------------
// Flash attention with tf32 mma.sync (R5 structure; P loads raw = rz trunc)
// ---------------------------------------------------------------------------
#define KSS 68
#define VSS 72
#define PSS 68
#define OFF_K0 0
#define OFF_K1 (64 * KSS)
#define OFF_V0 (2 * 64 * KSS)
#define OFF_V1 (2 * 64 * KSS + 64 * VSS)
#define OFF_P  (2 * 64 * KSS + 2 * 64 * VSS)
#define ATTN_SMEM ((2 * 64 * KSS + 2 * 64 * VSS + 64 * PSS) * 4)

__global__ void __launch_bounds__(128, 2) attn_mma(
    const float* __restrict__ q, const float* __restrict__ k,
    const float* __restrict__ v, float* __restrict__ o)
{
    extern __shared__ float sm[];
    float* Ks[2] = { sm + OFF_K0, sm + OFF_K1 };
    float* Vs[2] = { sm + OFF_V0, sm + OFF_V1 };
    float* Ps    = sm + OFF_P;

    const int tid  = threadIdx.x;
    const int lane = tid & 31;
    const int wid  = tid >> 5;
    const int wm   = wid * 16;
    const int tg   = lane >> 2;
    const int tig  = lane & 3;

    const int h  = blockIdx.y;
    const int b  = blockIdx.z;
    const int q0 = blockIdx.x * 64;
    const size_t hb = (size_t)h * DKK;

    uint32_t qf[8][4];
    {
        size_t r0 = ((size_t)(b * SS + q0 + wm + tg)) * DD + hb;
        size_t r8 = r0 + (size_t)8 * DD;
        #pragma unroll
        for (int ks = 0; ks < 8; ks++) {
            int c = ks * 8 + tig;
            qf[ks][0] = __float_as_uint(q[r0 + c    ] * 0.125f);
            qf[ks][1] = __float_as_uint(q[r8 + c    ] * 0.125f);
            qf[ks][2] = __float_as_uint(q[r0 + c + 4] * 0.125f);
            qf[ks][3] = __float_as_uint(q[r8 + c + 4] * 0.125f);
        }
    }

    float oacc[8][4];
    #pragma unroll
    for (int ni = 0; ni < 8; ni++)
        #pragma unroll
        for (int r = 0; r < 4; r++) oacc[ni][r] = 0.f;
    float m0 = -1e30f, m1 = -1e30f, l0 = 0.f, l1 = 0.f;

    const size_t kvbase = ((size_t)(b * SS)) * DD + hb;

    #define KV_PREFETCH(bf, kt) do {                                          \
        const float* kg = k + kvbase + (size_t)((kt) * 64) * DD;              \
        const float* vg = v + kvbase + (size_t)((kt) * 64) * DD;              \
        uint32_t kb = smem_u32(Ks[bf]);                                       \
        uint32_t vb = smem_u32(Vs[bf]);                                       \
        _Pragma("unroll")                                                     \
        for (int i = 0; i < 8; i++) {                                         \
            int e = tid + i * 128;                                            \
            int row = e >> 4, c = e & 15;                                     \
            cp16(kb + row * (KSS * 4) + c * 16, kg + (size_t)row * DD + c * 4);\
            cp16(vb + row * (VSS * 4) + c * 16, vg + (size_t)row * DD + c * 4);\
        }                                                                     \
        asm volatile("cp.async.commit_group;");                               \
    } while (0)

    KV_PREFETCH(0, 0);

    const int NT = SS / 64;
    for (int kt = 0; kt < NT; kt++) {
        int cur = kt & 1;
        asm volatile("cp.async.wait_group 0;");
        __syncthreads();
        if (kt + 1 < NT) KV_PREFETCH(cur ^ 1, kt + 1);

        float sacc[8][4];
        #pragma unroll
        for (int ni = 0; ni < 8; ni++)
            #pragma unroll
            for (int r = 0; r < 4; r++) sacc[ni][r] = 0.f;

        const float* Kc = Ks[cur];
        #pragma unroll
        for (int ks = 0; ks < 8; ks++) {
            int kc = ks * 8;
            #pragma unroll
            for (int ni = 0; ni < 8; ni++) {
                uint32_t bf2[2];
                int cn = ni * 8 + tg;
                bf2[0] = __float_as_uint(Kc[cn * KSS + kc + tig]);
                bf2[1] = __float_as_uint(Kc[cn * KSS + kc + 4 + tig]);
                mma_tf32(sacc[ni], qf[ks], bf2);
            }
        }

        float rmax0 = -1e30f, rmax1 = -1e30f;
        #pragma unroll
        for (int ni = 0; ni < 8; ni++) {
            rmax0 = fmaxf(rmax0, fmaxf(sacc[ni][0], sacc[ni][1]));
            rmax1 = fmaxf(rmax1, fmaxf(sacc[ni][2], sacc[ni][3]));
        }
        #pragma unroll
        for (int d = 1; d < 4; d <<= 1) {
            rmax0 = fmaxf(rmax0, __shfl_xor_sync(0xFFFFFFFFu, rmax0, d));
            rmax1 = fmaxf(rmax1, __shfl_xor_sync(0xFFFFFFFFu, rmax1, d));
        }
        float nm0 = fmaxf(m0, rmax0);
        float nm1 = fmaxf(m1, rmax1);
        float corr0 = __expf(m0 - nm0);
        float corr1 = __expf(m1 - nm1);

        float rsum0 = 0.f, rsum1 = 0.f;
        #pragma unroll
        for (int ni = 0; ni < 8; ni++) {
            float p0 = __expf(sacc[ni][0] - nm0);
            float p1 = __expf(sacc[ni][1] - nm0);
            float p2 = __expf(sacc[ni][2] - nm1);
            float p3 = __expf(sacc[ni][3] - nm1);
            rsum0 += p0 + p1;
            rsum1 += p2 + p3;
            float* pr0 = Ps + (wm + tg) * PSS + ni * 8 + 2 * tig;
            float* pr1 = Ps + (wm + tg + 8) * PSS + ni * 8 + 2 * tig;
            pr0[0] = p0; pr0[1] = p1;
            pr1[0] = p2; pr1[1] = p3;
        }
        #pragma unroll
        for (int d = 1; d < 4; d <<= 1) {
            rsum0 += __shfl_xor_sync(0xFFFFFFFFu, rsum0, d);
            rsum1 += __shfl_xor_sync(0xFFFFFFFFu, rsum1, d);
        }
        l0 = l0 * corr0 + rsum0;
        l1 = l1 * corr1 + rsum1;
        m0 = nm0; m1 = nm1;

        #pragma unroll
        for (int ni = 0; ni < 8; ni++) {
            oacc[ni][0] *= corr0; oacc[ni][1] *= corr0;
            oacc[ni][2] *= corr1; oacc[ni][3] *= corr1;
        }

        __syncwarp();

        // O += P @ V  (P loaded raw; HW tf32 truncation — error ~2^-11, fine)
        const float* Vc = Vs[cur];
        #pragma unroll
        for (int ks = 0; ks < 8; ks++) {
            int kc = ks * 8;
            uint32_t af[4];
            af[0] = __float_as_uint(Ps[(wm + tg    ) * PSS + kc + tig]);
            af[1] = __float_as_uint(Ps[(wm + tg + 8) * PSS + kc + tig]);
            af[2] = __float_as_uint(Ps[(wm + tg    ) * PSS + kc + 4 + tig]);
            af[3] = __float_as_uint(Ps[(wm + tg + 8) * PSS + kc + 4 + tig]);
            #pragma unroll
            for (int ni = 0; ni < 8; ni++) {
                uint32_t bf2[2];
                int cn = ni * 8 + tg;
                bf2[0] = __float_as_uint(Vc[(kc + tig    ) * VSS + cn]);
                bf2[1] = __float_as_uint(Vc[(kc + 4 + tig) * VSS + cn]);
                mma_tf32(oacc[ni], af, bf2);
            }
        }
        __syncwarp();
    }

    float inv0 = 1.f / l0;
    float inv1 = 1.f / l1;
    size_t r0 = ((size_t)(b * SS + q0 + wm + tg)) * DD + hb;
    size_t r8 = r0 + (size_t)8 * DD;
    #pragma unroll
    for (int ni = 0; ni < 8; ni++) {
        int c = ni * 8 + 2 * tig;
        float2 o0; o0.x = rtf(oacc[ni][0] * inv0); o0.y = rtf(oacc[ni][1] * inv0);
        float2 o1; o1.x = rtf(oacc[ni][2] * inv1); o1.y = rtf(oacc[ni][3] * inv1);
        *(float2*)(o + r0 + c) = o0;
        *(float2*)(o + r8 + c) = o1;
    }
    #undef KV_PREFETCH
}

// ---------------------------------------------------------------------------
// Host orchestration
// ---------------------------------------------------------------------------
extern "C" void kernel_launch(void* const* d_in, const int* in_sizes, int n_in,
                              void* d_out, int out_size)
{
    (void)in_sizes; (void)n_in; (void)out_size;

    const float* x  = (const float*)d_in[0];
    const float* wq = (const float*)d_in[1];
    const float* bq = (const float*)d_in[2];
    const float* wk = (const float*)d_in[3];
    const float* bk = (const float*)d_in[4];
    const float* wv = (const float*)d_in[5];
    const float* bv = (const float*)d_in[6];
    const float* wo = (const float*)d_in[7];
    const float* bo = (const float*)d_in[8];
    const float* w1 = (const float*)d_in[9];
    const float* b1 = (const float*)d_in[10];
    const float* w2 = (const float*)d_in[11];
    const float* b2 = (const float*)d_in[12];
    const float* g1 = (const float*)d_in[13];
    const float* g2 = (const float*)d_in[14];
    float* out = (float*)d_out;

    float *ph, *pq, *pk, *pv, *po, *px2, *ph2, *pff;
    float *prwq, *prwk, *prwv, *prwo, *prw1, *prw2;
    cudaGetSymbolAddress((void**)&ph,  g_h);
    cudaGetSymbolAddress((void**)&pq,  g_q);
    cudaGetSymbolAddress((void**)&pk,  g_k);
    cudaGetSymbolAddress((void**)&pv,  g_v);
    cudaGetSymbolAddress((void**)&po,  g_o);
    cudaGetSymbolAddress((void**)&px2, g_x2);
    cudaGetSymbolAddress((void**)&ph2, g_h2);
    cudaGetSymbolAddress((void**)&pff, g_ff);
    cudaGetSymbolAddress((void**)&prwq, g_rwq);
    cudaGetSymbolAddress((void**)&prwk, g_rwk);
    cudaGetSymbolAddress((void**)&prwv, g_rwv);
    cudaGetSymbolAddress((void**)&prwo, g_rwo);
    cudaGetSymbolAddress((void**)&prw1, g_rw1);
    cudaGetSymbolAddress((void**)&prw2, g_rw2);

    cudaFuncSetAttribute(attn_mma,
        cudaFuncAttributeMaxDynamicSharedMemorySize, ATTN_SMEM);

    dim3 gD(DD / BN,   MM / BM);   // (8, 32)
    dim3 gF(DFFF / BN, MM / BM);   // (32, 32)

    // 1) round all weights to tf32 in one pass
    round_all_kernel<<<ROUND_BLOCKS, 256>>>(
        wq, wk, wv, wo, w1, w2, prwq, prwk, prwv, prwo, prw1, prw2);

    // 2) h = rmsnorm(x, g1)
    rmsnorm_kernel<<<MM, 256>>>(x, g1, ph);

    // 3) fused QKV projections
    gemm_qkv<<<dim3(24, MM / BM), 256>>>(
        ph, prwq, prwk, prwv, bq, bk, bv, pq, pk, pv);

    // 4) RoPE
    rope_kernel<<<(MM * HH * 32) / 256, 256>>>(pq, pk);

    // 5) attention
    attn_mma<<<dim3(SS / 64, HH, BB), 128, ATTN_SMEM>>>(pq, pk, pv, po);

    // 6) x2 = x + o @ wo + bo
    gemm_mma<<<gD, 256>>>(po, prwo, bo, x, px2, DD, DD, 2, 0);

    // 7) h2 = rmsnorm(x2, g2)
    rmsnorm_kernel<<<MM, 256>>>(px2, g2, ph2);

    // 8) ff = relu(h2 @ w1 + b1)  (tf32-rounded)
    gemm_mma<<<gF, 256>>>(ph2, prw1, b1, nullptr, pff, DFFF, DD, 1, 1);

    // 9) out = x2 + ff @ w2 + b2
    gemm_mma<<<gD, 256>>>(pff, prw2, b2, px2, out, DD, DFFF, 2, 0);
}

// round 9
// speedup vs baseline: 1.1802x; 1.0324x over previous
#include <cuda_runtime.h>
#include <cuda_bf16.h>
#include <cstdint>
#include <math.h>

// Problem constants
#define BB   2
#define SS   2048
#define DD   1024
#define HH   16
#define DKK  64
#define DFFF 4096
#define MM   (BB * SS)          // 4096 rows
#define EPSF 1.1920929e-07f

// ---------------------------------------------------------------------------
// Scratch (device globals — no cudaMalloc allowed)
// ---------------------------------------------------------------------------
__device__ float g_h  [MM * DD];
__device__ float g_q  [MM * DD];
__device__ float g_k  [MM * DD];
__device__ float g_v  [MM * DD];
__device__ float g_o  [MM * DD];
__device__ float g_x2 [MM * DD];
__device__ float g_h2 [MM * DD];
__device__ float g_ff [MM * DFFF];
// tf32-pre-rounded weights (original [K,N] layout)
__device__ float g_rwq[DD * DD];
__device__ float g_rwk[DD * DD];
__device__ float g_rwv[DD * DD];
__device__ float g_rwo[DD * DD];
__device__ float g_rw1[DD * DFFF];
__device__ float g_rw2[DFFF * DD];

// ---------------------------------------------------------------------------
// helpers
// ---------------------------------------------------------------------------
__device__ __forceinline__ uint32_t smem_u32(const void* p) {
    uint32_t a;
    asm("{ .reg .u64 t; cvta.to.shared.u64 t, %1; cvt.u32.u64 %0, t; }"
        : "=r"(a) : "l"(p));
    return a;
}
__device__ __forceinline__ void cp16(uint32_t saddr, const void* g) {
    asm volatile("cp.async.cg.shared.global [%0], [%1], 16;" :: "r"(saddr), "l"(g));
}
__device__ __forceinline__ uint32_t f2tf32(float f) {
    uint32_t r;
    asm("cvt.rna.tf32.f32 %0, %1;" : "=r"(r) : "f"(f));
    return r;
}
__device__ __forceinline__ float rtf(float f) {
    return __uint_as_float(f2tf32(f));
}
__device__ __forceinline__ void mma_tf32(
    float* c, const uint32_t* a, const uint32_t* b)
{
    asm volatile(
        "mma.sync.aligned.m16n8k8.row.col.f32.tf32.tf32.f32 "
        "{%0,%1,%2,%3}, {%4,%5,%6,%7}, {%8,%9}, {%0,%1,%2,%3};"
        : "+f"(c[0]), "+f"(c[1]), "+f"(c[2]), "+f"(c[3])
        : "r"(a[0]), "r"(a[1]), "r"(a[2]), "r"(a[3]), "r"(b[0]), "r"(b[1]));
}

// ---------------------------------------------------------------------------
// Fused tf32 rounding for all 6 weights in one launch.
// ---------------------------------------------------------------------------
#define SEG  262144                 // (DD*DD)/4
#define SEGF 1048576                // (DD*DFFF)/4
__global__ void __launch_bounds__(256) round_all_kernel(
    const float* __restrict__ s0, const float* __restrict__ s1,
    const float* __restrict__ s2, const float* __restrict__ s3,
    const float* __restrict__ s4, const float* __restrict__ s5,
    float* __restrict__ d0, float* __restrict__ d1,
    float* __restrict__ d2, float* __restrict__ d3,
    float* __restrict__ d4, float* __restrict__ d5)
{
    long long i = (long long)blockIdx.x * 256 + threadIdx.x;
    const float4* src;
    float4* dst;
    long long off;
    if      (i < 1 * SEG) { src = (const float4*)s0; dst = (float4*)d0; off = i; }
    else if (i < 2 * SEG) { src = (const float4*)s1; dst = (float4*)d1; off = i - 1 * SEG; }
    else if (i < 3 * SEG) { src = (const float4*)s2; dst = (float4*)d2; off = i - 2 * SEG; }
    else if (i < 4 * SEG) { src = (const float4*)s3; dst = (float4*)d3; off = i - 3 * SEG; }
    else if (i < 4 * SEG + SEGF) { src = (const float4*)s4; dst = (float4*)d4; off = i - 4 * SEG; }
    else                   { src = (const float4*)s5; dst = (float4*)d5; off = i - 4 * SEG - SEGF; }
    float4 v = src[off];
    v.x = rtf(v.x); v.y = rtf(v.y); v.z = rtf(v.z); v.w = rtf(v.w);
    dst[off] = v;
}
#define ROUND_BLOCKS ((4 * SEG + 2 * SEGF) / 256)

// ---------------------------------------------------------------------------
// tf32 mma.sync GEMM — R5 inner loop, 4-stage cp.async pipeline (dyn smem).
// C[M,N] = A[M,K] @ B[K,N] + bias (+relu / +residual)
// CTA 128x128, BK=16, 256 threads (2x4 warps, 64x32 warp tile), 2 CTAs/SM.
// epi: 0 = bias, 1 = bias+relu, 2 = bias+residual. rnd: round output to tf32.
// ---------------------------------------------------------------------------
#define BM 128
#define BN 128
#define BK 16
#define APAD 20
#define BPAD 136
#define NSTG 4
#define A_FLTS (BM * APAD)                  // 2560
#define B_FLTS (BK * BPAD)                  // 2176
#define STG_FLTS (A_FLTS + B_FLTS)          // 4736
#define GEMM_SMEM (NSTG * STG_FLTS * 4)     // 75776 bytes

__device__ __forceinline__ void gemm_core(
    const float* __restrict__ A, const float* __restrict__ Bm,
    const float* __restrict__ bias, const float* __restrict__ res,
    float* __restrict__ C, int Nd, int Kd, int brow, int bcol,
    int epi, bool rnd, float* sm)
{
    const int tid  = threadIdx.x;
    const int lane = tid & 31;
    const int wid  = tid >> 5;
    const int warp_m = (wid >> 2) * 64;
    const int warp_n = (wid & 3) * 32;
    const int KT = Kd / BK;

    const int tg  = lane >> 2;
    const int tig = lane & 3;

    float acc[4][4][4];
    #pragma unroll
    for (int i = 0; i < 4; i++)
        #pragma unroll
        for (int j = 0; j < 4; j++)
            #pragma unroll
            for (int r = 0; r < 4; r++) acc[i][j][r] = 0.f;

    // stage s: A at sm + s*STG_FLTS, B at sm + s*STG_FLTS + A_FLTS
    #define COPY_STAGE(s, kt) do {                                             \
        float* sA = sm + (s) * STG_FLTS;                                       \
        float* sB = sA + A_FLTS;                                               \
        int k0 = (kt) * BK;                                                    \
        _Pragma("unroll")                                                      \
        for (int i = 0; i < 2; i++) {                                          \
            int e = tid + i * 256;                                             \
            int m = e >> 2, c4 = (e & 3) << 2;                                 \
            cp16(smem_u32(sA + m * APAD + c4),                                 \
                 A + (size_t)(brow + m) * Kd + k0 + c4);                       \
        }                                                                      \
        _Pragma("unroll")                                                      \
        for (int i = 0; i < 2; i++) {                                          \
            int e = tid + i * 256;                                             \
            int kr = e >> 5, c4 = (e & 31) << 2;                               \
            cp16(smem_u32(sB + kr * BPAD + c4),                                \
                 Bm + (size_t)(k0 + kr) * Nd + bcol + c4);                     \
        }                                                                      \
        asm volatile("cp.async.commit_group;");                                \
    } while (0)

    // prologue: stages 0,1,2 in flight
    COPY_STAGE(0, 0);
    COPY_STAGE(1, 1);
    COPY_STAGE(2, 2);

    for (int kt = 0; kt < KT; kt++) {
        int s = kt & (NSTG - 1);
        // issue stage kt+3 into buffer (kt-1)%4 (consumed last iteration,
        // protected by the trailing __syncthreads of that iteration)
        if (kt + 3 < KT) COPY_STAGE((kt + 3) & (NSTG - 1), kt + 3);

        // wait until stage kt is complete (groups complete in order)
        int ahead = KT - 1 - kt;         // groups issued after stage kt
        if (ahead >= 3)      asm volatile("cp.async.wait_group 3;");
        else if (ahead == 2) asm volatile("cp.async.wait_group 2;");
        else if (ahead == 1) asm volatile("cp.async.wait_group 1;");
        else                 asm volatile("cp.async.wait_group 0;");
        __syncthreads();

        const float* As = sm + s * STG_FLTS;
        const float* Bs = As + A_FLTS;

        #pragma unroll
        for (int ks = 0; ks < 2; ks++) {
            int kc = ks * 8;
            uint32_t af[4][4], bf[4][2];
            #pragma unroll
            for (int mi = 0; mi < 4; mi++) {
                int rm = warp_m + mi * 16 + tg;
                af[mi][0] = __float_as_uint(As[(rm    ) * APAD + kc + tig]);
                af[mi][1] = __float_as_uint(As[(rm + 8) * APAD + kc + tig]);
                af[mi][2] = __float_as_uint(As[(rm    ) * APAD + kc + 4 + tig]);
                af[mi][3] = __float_as_uint(As[(rm + 8) * APAD + kc + 4 + tig]);
            }
            #pragma unroll
            for (int ni = 0; ni < 4; ni++) {
                int cn = warp_n + ni * 8 + tg;
                bf[ni][0] = __float_as_uint(Bs[(kc + tig    ) * BPAD + cn]);
                bf[ni][1] = __float_as_uint(Bs[(kc + 4 + tig) * BPAD + cn]);
            }
            #pragma unroll
            for (int mi = 0; mi < 4; mi++)
                #pragma unroll
                for (int ni = 0; ni < 4; ni++)
                    mma_tf32(acc[mi][ni], af[mi], bf[ni]);
        }
        __syncthreads();
    }

    #pragma unroll
    for (int mi = 0; mi < 4; mi++) {
        int row0 = brow + warp_m + mi * 16 + tg;
        #pragma unroll
        for (int ni = 0; ni < 4; ni++) {
            int col = bcol + warp_n + ni * 8 + tig * 2;
            float2 bv = *(const float2*)(bias + col);
            #pragma unroll
            for (int half = 0; half < 2; half++) {
                int row = row0 + half * 8;
                float v0 = acc[mi][ni][half * 2 + 0] + bv.x;
                float v1 = acc[mi][ni][half * 2 + 1] + bv.y;
                if (epi == 1) { v0 = fmaxf(v0, 0.f); v1 = fmaxf(v1, 0.f); }
                if (epi == 2) {
                    float2 rv = *(const float2*)(res + (size_t)row * Nd + col);
                    v0 += rv.x; v1 += rv.y;
                }
                if (rnd) { v0 = rtf(v0); v1 = rtf(v1); }
                float2 o2; o2.x = v0; o2.y = v1;
                *(float2*)(C + (size_t)row * Nd + col) = o2;
            }
        }
    }
    #undef COPY_STAGE
}

__global__ void __launch_bounds__(256, 2) gemm_mma(
    const float* __restrict__ A, const float* __restrict__ Bm,
    const float* __restrict__ bias, const float* __restrict__ res,
    float* __restrict__ C, int Nd, int Kd, int epi, int rnd)
{
    extern __shared__ float sm[];
    gemm_core(A, Bm, bias, res, C, Nd, Kd,
              blockIdx.y * BM, blockIdx.x * BN, epi, rnd != 0, sm);
}

// Fused QKV: grid.x in [0,24); nsel = x>>3 picks (wq,wk,wv).
__global__ void __launch_bounds__(256, 2) gemm_qkv(
    const float* __restrict__ A,
    const float* __restrict__ Bq, const float* __restrict__ Bk,
    const float* __restrict__ Bv,
    const float* __restrict__ bq, const float* __restrict__ bk,
    const float* __restrict__ bv,
    float* __restrict__ Cq, float* __restrict__ Ck, float* __restrict__ Cv)
{
    extern __shared__ float sm[];
    int nsel = blockIdx.x >> 3;
    int bcol = (blockIdx.x & 7) * BN;
    const float* B  = (nsel == 0) ? Bq : (nsel == 1) ? Bk : Bv;
    const float* bi = (nsel == 0) ? bq : (nsel == 1) ? bk : bv;
    float* C        = (nsel == 0) ? Cq : (nsel == 1) ? Ck : Cv;
    gemm_core(A, B, bi, nullptr, C, DD, DD,
              blockIdx.y * BM, bcol, 0, nsel == 2, sm);
}

// ---------------------------------------------------------------------------
// RMSNorm (outputs tf32-rounded)
// ---------------------------------------------------------------------------
__global__ void __launch_bounds__(256) rmsnorm_kernel(
    const float* __restrict__ x, const float* __restrict__ g,
    float* __restrict__ out)
{
    int row = blockIdx.x;
    const float4* xr = (const float4*)(x + (size_t)row * DD);
    float4 xv = xr[threadIdx.x];
    float ss = xv.x * xv.x + xv.y * xv.y + xv.z * xv.z + xv.w * xv.w;
    #pragma unroll
    for (int off = 16; off > 0; off >>= 1)
        ss += __shfl_xor_sync(0xFFFFFFFFu, ss, off);
    __shared__ float sred[8];
    __shared__ float sscale;
    int warp = threadIdx.x >> 5;
    if ((threadIdx.x & 31) == 0) sred[warp] = ss;
    __syncthreads();
    if (threadIdx.x == 0) {
        float t = 0.f;
        #pragma unroll
        for (int i = 0; i < 8; i++) t += sred[i];
        sscale = rsqrtf(t / (float)DD + EPSF);
    }
    __syncthreads();
    float sc = sscale;
    float4 gv = ((const float4*)g)[threadIdx.x];
    float4 ov;
    ov.x = rtf(xv.x * sc * gv.x); ov.y = rtf(xv.y * sc * gv.y);
    ov.z = rtf(xv.z * sc * gv.z); ov.w = rtf(xv.w * sc * gv.w);
    ((float4*)(out + (size_t)row * DD))[threadIdx.x] = ov;
}

// ---------------------------------------------------------------------------
// RoPE (outputs tf32-rounded); inv_freq via exp2f (MUFU), not powf
// ---------------------------------------------------------------------------
#define LOG2_10000_OVER_32 0.41524101186092029f
__global__ void rope_kernel(float* __restrict__ q, float* __restrict__ k)
{
    int idx = blockIdx.x * blockDim.x + threadIdx.x;
    int j   = idx & 31;
    int h   = (idx >> 5) & (HH - 1);
    int row = idx >> 9;
    int s   = row & (SS - 1);
    float inv_freq = exp2f(-(float)j * LOG2_10000_OVER_32);
    float ang = (float)s * inv_freq;
    float sn, cs;
    sincosf(ang, &sn, &cs);
    size_t base = (size_t)row * DD + h * DKK + j;
    float q1 = q[base], q2 = q[base + 32];
    q[base]      = rtf(q1 * cs - q2 * sn);
    q[base + 32] = rtf(q2 * cs + q1 * sn);
    float k1 = k[base], k2 = k[base + 32];
    k[base]      = rtf(k1 * cs - k2 * sn);
    k[base + 32] = rtf(k2 * cs + k1 * sn);
}

// ---------------------------------------------------------------------------
// Flash attention with tf32 mma.sync (unchanged from R8)
// ---------------------------------------------------------------------------
#define KSS 68
#define VSS 72
#define PSS 68
#define OFF_K0 0
#define OFF_K1 (64 * KSS)
#define OFF_V0 (2 * 64 * KSS)
#define OFF_V1 (2 * 64 * KSS + 64 * VSS)
#define OFF_P  (2 * 64 * KSS + 2 * 64 * VSS)
#define ATTN_SMEM ((2 * 64 * KSS + 2 * 64 * VSS + 64 * PSS) * 4)

__global__ void __launch_bounds__(128, 2) attn_mma(
    const float* __restrict__ q, const float* __restrict__ k,
    const float* __restrict__ v, float* __restrict__ o)
{
    extern __shared__ float sm[];
    float* Ks[2] = { sm + OFF_K0, sm + OFF_K1 };
    float* Vs[2] = { sm + OFF_V0, sm + OFF_V1 };
    float* Ps    = sm + OFF_P;

    const int tid  = threadIdx.x;
    const int lane = tid & 31;
    const int wid  = tid >> 5;
    const int wm   = wid * 16;
    const int tg   = lane >> 2;
    const int tig  = lane & 3;

    const int h  = blockIdx.y;
    const int b  = blockIdx.z;
    const int q0 = blockIdx.x * 64;
    const size_t hb = (size_t)h * DKK;

    uint32_t qf[8][4];
    {
        size_t r0 = ((size_t)(b * SS + q0 + wm + tg)) * DD + hb;
        size_t r8 = r0 + (size_t)8 * DD;
        #pragma unroll
        for (int ks = 0; ks < 8; ks++) {
            int c = ks * 8 + tig;
            qf[ks][0] = __float_as_uint(q[r0 + c    ] * 0.125f);
            qf[ks][1] = __float_as_uint(q[r8 + c    ] * 0.125f);
            qf[ks][2] = __float_as_uint(q[r0 + c + 4] * 0.125f);
            qf[ks][3] = __float_as_uint(q[r8 + c + 4] * 0.125f);
        }
    }

    float oacc[8][4];
    #pragma unroll
    for (int ni = 0; ni < 8; ni++)
        #pragma unroll
        for (int r = 0; r < 4; r++) oacc[ni][r] = 0.f;
    float m0 = -1e30f, m1 = -1e30f, l0 = 0.f, l1 = 0.f;

    const size_t kvbase = ((size_t)(b * SS)) * DD + hb;

    #define KV_PREFETCH(bf, kt) do {                                          \
        const float* kg = k + kvbase + (size_t)((kt) * 64) * DD;              \
        const float* vg = v + kvbase + (size_t)((kt) * 64) * DD;              \
        uint32_t kb = smem_u32(Ks[bf]);                                       \
        uint32_t vb = smem_u32(Vs[bf]);                                       \
        _Pragma("unroll")                                                     \
        for (int i = 0; i < 8; i++) {                                         \
            int e = tid + i * 128;                                            \
            int row = e >> 4, c = e & 15;                                     \
            cp16(kb + row * (KSS * 4) + c * 16, kg + (size_t)row * DD + c * 4);\
            cp16(vb + row * (VSS * 4) + c * 16, vg + (size_t)row * DD + c * 4);\
        }                                                                     \
        asm volatile("cp.async.commit_group;");                               \
    } while (0)

    KV_PREFETCH(0, 0);

    const int NT = SS / 64;
    for (int kt = 0; kt < NT; kt++) {
        int cur = kt & 1;
        asm volatile("cp.async.wait_group 0;");
        __syncthreads();
        if (kt + 1 < NT) KV_PREFETCH(cur ^ 1, kt + 1);

        float sacc[8][4];
        #pragma unroll
        for (int ni = 0; ni < 8; ni++)
            #pragma unroll
            for (int r = 0; r < 4; r++) sacc[ni][r] = 0.f;

        const float* Kc = Ks[cur];
        #pragma unroll
        for (int ks = 0; ks < 8; ks++) {
            int kc = ks * 8;
            #pragma unroll
            for (int ni = 0; ni < 8; ni++) {
                uint32_t bf2[2];
                int cn = ni * 8 + tg;
                bf2[0] = __float_as_uint(Kc[cn * KSS + kc + tig]);
                bf2[1] = __float_as_uint(Kc[cn * KSS + kc + 4 + tig]);
                mma_tf32(sacc[ni], qf[ks], bf2);
            }
        }

        float rmax0 = -1e30f, rmax1 = -1e30f;
        #pragma unroll
        for (int ni = 0; ni < 8; ni++) {
            rmax0 = fmaxf(rmax0, fmaxf(sacc[ni][0], sacc[ni][1]));
            rmax1 = fmaxf(rmax1, fmaxf(sacc[ni][2], sacc[ni][3]));
        }
        #pragma unroll
        for (int d = 1; d < 4; d <<= 1) {
            rmax0 = fmaxf(rmax0, __shfl_xor_sync(0xFFFFFFFFu, rmax0, d));
            rmax1 = fmaxf(rmax1, __shfl_xor_sync(0xFFFFFFFFu, rmax1, d));
        }
        float nm0 = fmaxf(m0, rmax0);
        float nm1 = fmaxf(m1, rmax1);
        float corr0 = __expf(m0 - nm0);
        float corr1 = __expf(m1 - nm1);

        float rsum0 = 0.f, rsum1 = 0.f;
        #pragma unroll
        for (int ni = 0; ni < 8; ni++) {
            float p0 = __expf(sacc[ni][0] - nm0);
            float p1 = __expf(sacc[ni][1] - nm0);
            float p2 = __expf(sacc[ni][2] - nm1);
            float p3 = __expf(sacc[ni][3] - nm1);
            rsum0 += p0 + p1;
            rsum1 += p2 + p3;
            float* pr0 = Ps + (wm + tg) * PSS + ni * 8 + 2 * tig;
            float* pr1 = Ps + (wm + tg + 8) * PSS + ni * 8 + 2 * tig;
            pr0[0] = p0; pr0[1] = p1;
            pr1[0] = p2; pr1[1] = p3;
        }
        #pragma unroll
        for (int d = 1; d < 4; d <<= 1) {
            rsum0 += __shfl_xor_sync(0xFFFFFFFFu, rsum0, d);
            rsum1 += __shfl_xor_sync(0xFFFFFFFFu, rsum1, d);
        }
        l0 = l0 * corr0 + rsum0;
        l1 = l1 * corr1 + rsum1;
        m0 = nm0; m1 = nm1;

        #pragma unroll
        for (int ni = 0; ni < 8; ni++) {
            oacc[ni][0] *= corr0; oacc[ni][1] *= corr0;
            oacc[ni][2] *= corr1; oacc[ni][3] *= corr1;
        }

        __syncwarp();

        const float* Vc = Vs[cur];
        #pragma unroll
        for (int ks = 0; ks < 8; ks++) {
            int kc = ks * 8;
            uint32_t af[4];
            af[0] = __float_as_uint(Ps[(wm + tg    ) * PSS + kc + tig]);
            af[1] = __float_as_uint(Ps[(wm + tg + 8) * PSS + kc + tig]);
            af[2] = __float_as_uint(Ps[(wm + tg    ) * PSS + kc + 4 + tig]);
            af[3] = __float_as_uint(Ps[(wm + tg + 8) * PSS + kc + 4 + tig]);
            #pragma unroll
            for (int ni = 0; ni < 8; ni++) {
                uint32_t bf2[2];
                int cn = ni * 8 + tg;
                bf2[0] = __float_as_uint(Vc[(kc + tig    ) * VSS + cn]);
                bf2[1] = __float_as_uint(Vc[(kc + 4 + tig) * VSS + cn]);
                mma_tf32(oacc[ni], af, bf2);
            }
        }
        __syncwarp();
    }

    float inv0 = 1.f / l0;
    float inv1 = 1.f / l1;
    size_t r0 = ((size_t)(b * SS + q0 + wm + tg)) * DD + hb;
    size_t r8 = r0 + (size_t)8 * DD;
    #pragma unroll
    for (int ni = 0; ni < 8; ni++) {
        int c = ni * 8 + 2 * tig;
        float2 o0; o0.x = rtf(oacc[ni][0] * inv0); o0.y = rtf(oacc[ni][1] * inv0);
        float2 o1; o1.x = rtf(oacc[ni][2] * inv1); o1.y = rtf(oacc[ni][3] * inv1);
        *(float2*)(o + r0 + c) = o0;
        *(float2*)(o + r8 + c) = o1;
    }
    #undef KV_PREFETCH
}

// ---------------------------------------------------------------------------
// Host orchestration
// ---------------------------------------------------------------------------
extern "C" void kernel_launch(void* const* d_in, const int* in_sizes, int n_in,
                              void* d_out, int out_size)
{
    (void)in_sizes; (void)n_in; (void)out_size;

    const float* x  = (const float*)d_in[0];
    const float* wq = (const float*)d_in[1];
    const float* bq = (const float*)d_in[2];
    const float* wk = (const float*)d_in[3];
    const float* bk = (const float*)d_in[4];
    const float* wv = (const float*)d_in[5];
    const float* bv = (const float*)d_in[6];
    const float* wo = (const float*)d_in[7];
    const float* bo = (const float*)d_in[8];
    const float* w1 = (const float*)d_in[9];
    const float* b1 = (const float*)d_in[10];
    const float* w2 = (const float*)d_in[11];
    const float* b2 = (const float*)d_in[12];
    const float* g1 = (const float*)d_in[13];
    const float* g2 = (const float*)d_in[14];
    float* out = (float*)d_out;

    float *ph, *pq, *pk, *pv, *po, *px2, *ph2, *pff;
    float *prwq, *prwk, *prwv, *prwo, *prw1, *prw2;
    cudaGetSymbolAddress((void**)&ph,  g_h);
    cudaGetSymbolAddress((void**)&pq,  g_q);
    cudaGetSymbolAddress((void**)&pk,  g_k);
    cudaGetSymbolAddress((void**)&pv,  g_v);
    cudaGetSymbolAddress((void**)&po,  g_o);
    cudaGetSymbolAddress((void**)&px2, g_x2);
    cudaGetSymbolAddress((void**)&ph2, g_h2);
    cudaGetSymbolAddress((void**)&pff, g_ff);
    cudaGetSymbolAddress((void**)&prwq, g_rwq);
    cudaGetSymbolAddress((void**)&prwk, g_rwk);
    cudaGetSymbolAddress((void**)&prwv, g_rwv);
    cudaGetSymbolAddress((void**)&prwo, g_rwo);
    cudaGetSymbolAddress((void**)&prw1, g_rw1);
    cudaGetSymbolAddress((void**)&prw2, g_rw2);

    cudaFuncSetAttribute(attn_mma,
        cudaFuncAttributeMaxDynamicSharedMemorySize, ATTN_SMEM);
    cudaFuncSetAttribute(gemm_mma,
        cudaFuncAttributeMaxDynamicSharedMemorySize, GEMM_SMEM);
    cudaFuncSetAttribute(gemm_qkv,
        cudaFuncAttributeMaxDynamicSharedMemorySize, GEMM_SMEM);

    dim3 gD(DD / BN,   MM / BM);   // (8, 32)
    dim3 gF(DFFF / BN, MM / BM);   // (32, 32)

    // 1) round all weights to tf32 in one pass
    round_all_kernel<<<ROUND_BLOCKS, 256>>>(
        wq, wk, wv, wo, w1, w2, prwq, prwk, prwv, prwo, prw1, prw2);

    // 2) h = rmsnorm(x, g1)
    rmsnorm_kernel<<<MM, 256>>>(x, g1, ph);

    // 3) fused QKV projections
    gemm_qkv<<<dim3(24, MM / BM), 256, GEMM_SMEM>>>(
        ph, prwq, prwk, prwv, bq, bk, bv, pq, pk, pv);

    // 4) RoPE
    rope_kernel<<<(MM * HH * 32) / 256, 256>>>(pq, pk);

    // 5) attention
    attn_mma<<<dim3(SS / 64, HH, BB), 128, ATTN_SMEM>>>(pq, pk, pv, po);

    // 6) x2 = x + o @ wo + bo
    gemm_mma<<<gD, 256, GEMM_SMEM>>>(po, prwo, bo, x, px2, DD, DD, 2, 0);

    // 7) h2 = rmsnorm(x2, g2)
    rmsnorm_kernel<<<MM, 256>>>(px2, g2, ph2);

    // 8) ff = relu(h2 @ w1 + b1)  (tf32-rounded)
    gemm_mma<<<gF, 256, GEMM_SMEM>>>(ph2, prw1, b1, nullptr, pff, DFFF, DD, 1, 1);

    // 9) out = x2 + ff @ w2 + b2
    gemm_mma<<<gD, 256, GEMM_SMEM>>>(pff, prw2, b2, px2, out, DD, DFFF, 2, 0);
}

// round 10
// speedup vs baseline: 1.6966x; 1.4375x over previous
#include <cuda_runtime.h>
#include <cuda_fp16.h>
#include <cstdint>
#include <math.h>

// Problem constants
#define BB   2
#define SS   2048
#define DD   1024
#define HH   16
#define DKK  64
#define DFFF 4096
#define MM   (BB * SS)          // 4096 rows
#define EPSF 1.1920929e-07f

// ---------------------------------------------------------------------------
// Scratch (device globals — no cudaMalloc allowed)
// ---------------------------------------------------------------------------
__device__ __half g_h  [MM * DD];    // rmsnorm1 out (half)
__device__ float  g_q  [MM * DD];
__device__ float  g_k  [MM * DD];
__device__ float  g_v  [MM * DD];
__device__ __half g_o  [MM * DD];    // attention out (half)
__device__ float  g_x2 [MM * DD];
__device__ __half g_h2 [MM * DD];    // rmsnorm2 out (half)
__device__ __half g_ff [MM * DFFF];  // relu FFN mid (half)
// fp16 pair-packed weights: [K/2][N] of half2 (low = even-k)
__device__ uint32_t g_pwq[DD * DD / 2];
__device__ uint32_t g_pwk[DD * DD / 2];
__device__ uint32_t g_pwv[DD * DD / 2];
__device__ uint32_t g_pwo[DD * DD / 2];
__device__ uint32_t g_pw1[DD * DFFF / 2];
__device__ uint32_t g_pw2[DFFF * DD / 2];

// ---------------------------------------------------------------------------
// helpers
// ---------------------------------------------------------------------------
__device__ __forceinline__ uint32_t smem_u32(const void* p) {
    uint32_t a;
    asm("{ .reg .u64 t; cvta.to.shared.u64 t, %1; cvt.u32.u64 %0, t; }"
        : "=r"(a) : "l"(p));
    return a;
}
__device__ __forceinline__ void cp16(uint32_t saddr, const void* g) {
    asm volatile("cp.async.cg.shared.global [%0], [%1], 16;" :: "r"(saddr), "l"(g));
}
__device__ __forceinline__ uint32_t f2tf32(float f) {
    uint32_t r;
    asm("cvt.rna.tf32.f32 %0, %1;" : "=r"(r) : "f"(f));
    return r;
}
__device__ __forceinline__ float rtf(float f) {
    return __uint_as_float(f2tf32(f));
}
__device__ __forceinline__ void mma_tf32(
    float* c, const uint32_t* a, const uint32_t* b)
{
    asm volatile(
        "mma.sync.aligned.m16n8k8.row.col.f32.tf32.tf32.f32 "
        "{%0,%1,%2,%3}, {%4,%5,%6,%7}, {%8,%9}, {%0,%1,%2,%3};"
        : "+f"(c[0]), "+f"(c[1]), "+f"(c[2]), "+f"(c[3])
        : "r"(a[0]), "r"(a[1]), "r"(a[2]), "r"(a[3]), "r"(b[0]), "r"(b[1]));
}
__device__ __forceinline__ void mma_f16(
    float* c, const uint32_t* a, const uint32_t* b)
{
    asm volatile(
        "mma.sync.aligned.m16n8k16.row.col.f32.f16.f16.f32 "
        "{%0,%1,%2,%3}, {%4,%5,%6,%7}, {%8,%9}, {%0,%1,%2,%3};"
        : "+f"(c[0]), "+f"(c[1]), "+f"(c[2]), "+f"(c[3])
        : "r"(a[0]), "r"(a[1]), "r"(a[2]), "r"(a[3]), "r"(b[0]), "r"(b[1]));
}
__device__ __forceinline__ uint32_t h2_bits(__half2 h) {
    return *reinterpret_cast<uint32_t*>(&h);
}

// ---------------------------------------------------------------------------
// Weight pack: fp32 [K][N] -> half2 [K/2][N]  (low half = even k)
// ---------------------------------------------------------------------------
__global__ void __launch_bounds__(256) pack_w_kernel(
    const float* __restrict__ w, uint32_t* __restrict__ out, int K, int N)
{
    int i  = blockIdx.x * 256 + threadIdx.x;    // elem in half2 space
    int k2 = i / N;
    int n  = i - k2 * N;
    float a = w[(size_t)(2 * k2)     * N + n];
    float b = w[(size_t)(2 * k2 + 1) * N + n];
    out[i] = h2_bits(__floats2half2_rn(a, b));
}

// ---------------------------------------------------------------------------
// fp16 mma.sync GEMM: C[M,N] = A[M,K] @ W[K,N] + bias (+relu / +residual)
// A: [M][K] half. W: pair-packed half2 [K/2][N].
// CTA 128x128, BK=32 (2 k16 steps), 256 threads (2x4 warps, 64x32 warp tile),
// 4-stage cp.async pipeline, 2 CTAs/SM.
// epi: 0=bias, 1=bias+relu, 2=bias+residual
// outm: 0=fp32, 1=fp32 tf32-rounded, 2=half
// ---------------------------------------------------------------------------
#define BM 128
#define BN 128
#define BK 32
#define ASTRH 40                            // A smem row stride (halves)
#define BNP 136                             // B smem pair-row stride (half2)
#define A_WORDS (BM * ASTRH / 2)            // 2560
#define B_WORDS (16 * BNP)                  // 2176
#define STG_WORDS (A_WORDS + B_WORDS)       // 4736
#define NSTG 4
#define GEMM_SMEM (NSTG * STG_WORDS * 4)    // 75776 bytes

__device__ __forceinline__ void gemm_core(
    const __half* __restrict__ A, const uint32_t* __restrict__ Bp,
    const float* __restrict__ bias, const float* __restrict__ res,
    void* __restrict__ C, int Nd, int Kd, int brow, int bcol,
    int epi, int outm, uint32_t* sm)
{
    const int tid  = threadIdx.x;
    const int lane = tid & 31;
    const int wid  = tid >> 5;
    const int warp_m = (wid >> 2) * 64;
    const int warp_n = (wid & 3) * 32;
    const int KT = Kd / BK;

    const int tg  = lane >> 2;
    const int tig = lane & 3;

    float acc[4][4][4];
    #pragma unroll
    for (int i = 0; i < 4; i++)
        #pragma unroll
        for (int j = 0; j < 4; j++)
            #pragma unroll
            for (int r = 0; r < 4; r++) acc[i][j][r] = 0.f;

    // stage s: A halves at sm + s*STG_WORDS (as half*), B words after A_WORDS
    #define COPY_STAGE(s, kt) do {                                             \
        __half*   sA = (__half*)(sm + (s) * STG_WORDS);                        \
        uint32_t* sB = sm + (s) * STG_WORDS + A_WORDS;                         \
        int k0 = (kt) * BK;                                                    \
        _Pragma("unroll")                                                      \
        for (int i = 0; i < 2; i++) {         /* A: 128 x 32 halves */         \
            int e = tid + i * 256;                                             \
            int m = e >> 2, c8 = (e & 3) << 3;                                 \
            cp16(smem_u32(sA + m * ASTRH + c8),                                \
                 A + (size_t)(brow + m) * Kd + k0 + c8);                       \
        }                                                                      \
        _Pragma("unroll")                                                      \
        for (int i = 0; i < 2; i++) {         /* B: 16 pair-rows x 128 h2 */   \
            int e = tid + i * 256;                                             \
            int r = e >> 5, c4 = (e & 31) << 2;                                \
            cp16(smem_u32(sB + r * BNP + c4),                                  \
                 Bp + ((size_t)(k0 >> 1) + r) * Nd + bcol + c4);               \
        }                                                                      \
        asm volatile("cp.async.commit_group;");                                \
    } while (0)

    COPY_STAGE(0, 0);
    COPY_STAGE(1, 1);
    COPY_STAGE(2, 2);

    for (int kt = 0; kt < KT; kt++) {
        int s = kt & (NSTG - 1);
        if (kt + 3 < KT) COPY_STAGE((kt + 3) & (NSTG - 1), kt + 3);

        int ahead = KT - 1 - kt;
        if (ahead >= 3)      asm volatile("cp.async.wait_group 3;");
        else if (ahead == 2) asm volatile("cp.async.wait_group 2;");
        else if (ahead == 1) asm volatile("cp.async.wait_group 1;");
        else                 asm volatile("cp.async.wait_group 0;");
        __syncthreads();

        const __half*   As = (const __half*)(sm + s * STG_WORDS);
        const uint32_t* Bs = sm + s * STG_WORDS + A_WORDS;

        #pragma unroll
        for (int ks = 0; ks < 2; ks++) {           // two k16 steps per stage
            uint32_t af[4][4], bf[4][2];
            #pragma unroll
            for (int mi = 0; mi < 4; mi++) {
                int rm = warp_m + mi * 16 + tg;
                const __half* ap = As + rm * ASTRH + ks * 16 + 2 * tig;
                af[mi][0] = *(const uint32_t*)(ap);
                af[mi][1] = *(const uint32_t*)(ap + 8 * ASTRH);
                af[mi][2] = *(const uint32_t*)(ap + 8);
                af[mi][3] = *(const uint32_t*)(ap + 8 * ASTRH + 8);
            }
            #pragma unroll
            for (int ni = 0; ni < 4; ni++) {
                int cn = warp_n + ni * 8 + tg;
                bf[ni][0] = Bs[(ks * 8 + tig    ) * BNP + cn];
                bf[ni][1] = Bs[(ks * 8 + tig + 4) * BNP + cn];
            }
            #pragma unroll
            for (int mi = 0; mi < 4; mi++)
                #pragma unroll
                for (int ni = 0; ni < 4; ni++)
                    mma_f16(acc[mi][ni], af[mi], bf[ni]);
        }
        __syncthreads();
    }

    #pragma unroll
    for (int mi = 0; mi < 4; mi++) {
        int row0 = brow + warp_m + mi * 16 + tg;
        #pragma unroll
        for (int ni = 0; ni < 4; ni++) {
            int col = bcol + warp_n + ni * 8 + tig * 2;
            float2 bv = *(const float2*)(bias + col);
            #pragma unroll
            for (int half_ = 0; half_ < 2; half_++) {
                int row = row0 + half_ * 8;
                float v0 = acc[mi][ni][half_ * 2 + 0] + bv.x;
                float v1 = acc[mi][ni][half_ * 2 + 1] + bv.y;
                if (epi == 1) { v0 = fmaxf(v0, 0.f); v1 = fmaxf(v1, 0.f); }
                if (epi == 2) {
                    float2 rv = *(const float2*)(res + (size_t)row * Nd + col);
                    v0 += rv.x; v1 += rv.y;
                }
                if (outm == 2) {
                    *(__half2*)((__half*)C + (size_t)row * Nd + col) =
                        __floats2half2_rn(v0, v1);
                } else {
                    if (outm == 1) { v0 = rtf(v0); v1 = rtf(v1); }
                    float2 o2; o2.x = v0; o2.y = v1;
                    *(float2*)((float*)C + (size_t)row * Nd + col) = o2;
                }
            }
        }
    }
    #undef COPY_STAGE
}

__global__ void __launch_bounds__(256, 2) gemm_h(
    const __half* __restrict__ A, const uint32_t* __restrict__ Bp,
    const float* __restrict__ bias, const float* __restrict__ res,
    void* __restrict__ C, int Nd, int Kd, int epi, int outm)
{
    extern __shared__ uint32_t sm[];
    gemm_core(A, Bp, bias, res, C, Nd, Kd,
              blockIdx.y * BM, blockIdx.x * BN, epi, outm, sm);
}

// Fused QKV: grid.x in [0,24); nsel = x>>3 picks (wq,wk,wv). q,k,v fp32 out.
__global__ void __launch_bounds__(256, 2) gemm_qkv(
    const __half* __restrict__ A,
    const uint32_t* __restrict__ Bq, const uint32_t* __restrict__ Bk,
    const uint32_t* __restrict__ Bv,
    const float* __restrict__ bq, const float* __restrict__ bk,
    const float* __restrict__ bv,
    float* __restrict__ Cq, float* __restrict__ Ck, float* __restrict__ Cv)
{
    extern __shared__ uint32_t sm[];
    int nsel = blockIdx.x >> 3;
    int bcol = (blockIdx.x & 7) * BN;
    const uint32_t* B = (nsel == 0) ? Bq : (nsel == 1) ? Bk : Bv;
    const float* bi   = (nsel == 0) ? bq : (nsel == 1) ? bk : bv;
    float* C          = (nsel == 0) ? Cq : (nsel == 1) ? Ck : Cv;
    // v gets tf32-rounded (consumed raw by tf32 attention MMA); q,k in RoPE
    gemm_core(A, B, bi, nullptr, C, DD, DD,
              blockIdx.y * BM, bcol, 0, (nsel == 2) ? 1 : 0, sm);
}

// ---------------------------------------------------------------------------
// RMSNorm: fp32 in, half out (consumed only by fp16 GEMMs)
// ---------------------------------------------------------------------------
__global__ void __launch_bounds__(256) rmsnorm_h_kernel(
    const float* __restrict__ x, const float* __restrict__ g,
    __half* __restrict__ out)
{
    int row = blockIdx.x;
    const float4* xr = (const float4*)(x + (size_t)row * DD);
    float4 xv = xr[threadIdx.x];
    float ss = xv.x * xv.x + xv.y * xv.y + xv.z * xv.z + xv.w * xv.w;
    #pragma unroll
    for (int off = 16; off > 0; off >>= 1)
        ss += __shfl_xor_sync(0xFFFFFFFFu, ss, off);
    __shared__ float sred[8];
    __shared__ float sscale;
    int warp = threadIdx.x >> 5;
    if ((threadIdx.x & 31) == 0) sred[warp] = ss;
    __syncthreads();
    if (threadIdx.x == 0) {
        float t = 0.f;
        #pragma unroll
        for (int i = 0; i < 8; i++) t += sred[i];
        sscale = rsqrtf(t / (float)DD + EPSF);
    }
    __syncthreads();
    float sc = sscale;
    float4 gv = ((const float4*)g)[threadIdx.x];
    uint2 u;
    u.x = h2_bits(__floats2half2_rn(xv.x * sc * gv.x, xv.y * sc * gv.y));
    u.y = h2_bits(__floats2half2_rn(xv.z * sc * gv.z, xv.w * sc * gv.w));
    ((uint2*)(out + (size_t)row * DD))[threadIdx.x] = u;
}

// ---------------------------------------------------------------------------
// RoPE (q,k fp32; outputs tf32-rounded for the tf32 attention MMA)
// ---------------------------------------------------------------------------
#define LOG2_10000_OVER_32 0.41524101186092029f
__global__ void rope_kernel(float* __restrict__ q, float* __restrict__ k)
{
    int idx = blockIdx.x * blockDim.x + threadIdx.x;
    int j   = idx & 31;
    int h   = (idx >> 5) & (HH - 1);
    int row = idx >> 9;
    int s   = row & (SS - 1);
    float inv_freq = exp2f(-(float)j * LOG2_10000_OVER_32);
    float ang = (float)s * inv_freq;
    float sn, cs;
    sincosf(ang, &sn, &cs);
    size_t base = (size_t)row * DD + h * DKK + j;
    float q1 = q[base], q2 = q[base + 32];
    q[base]      = rtf(q1 * cs - q2 * sn);
    q[base + 32] = rtf(q2 * cs + q1 * sn);
    float k1 = k[base], k2 = k[base + 32];
    k[base]      = rtf(k1 * cs - k2 * sn);
    k[base + 32] = rtf(k2 * cs + k1 * sn);
}

// ---------------------------------------------------------------------------
// Flash attention, tf32 mma.sync (proven R8/R9 version; only change: half out)
// ---------------------------------------------------------------------------
#define KSS 68
#define VSS 72
#define PSS 68
#define OFF_K0 0
#define OFF_K1 (64 * KSS)
#define OFF_V0 (2 * 64 * KSS)
#define OFF_V1 (2 * 64 * KSS + 64 * VSS)
#define OFF_P  (2 * 64 * KSS + 2 * 64 * VSS)
#define ATTN_SMEM ((2 * 64 * KSS + 2 * 64 * VSS + 64 * PSS) * 4)

__global__ void __launch_bounds__(128, 2) attn_mma(
    const float* __restrict__ q, const float* __restrict__ k,
    const float* __restrict__ v, __half* __restrict__ o)
{
    extern __shared__ float smf[];
    float* Ks[2] = { smf + OFF_K0, smf + OFF_K1 };
    float* Vs[2] = { smf + OFF_V0, smf + OFF_V1 };
    float* Ps    = smf + OFF_P;

    const int tid  = threadIdx.x;
    const int lane = tid & 31;
    const int wid  = tid >> 5;
    const int wm   = wid * 16;
    const int tg   = lane >> 2;
    const int tig  = lane & 3;

    const int h  = blockIdx.y;
    const int b  = blockIdx.z;
    const int q0 = blockIdx.x * 64;
    const size_t hb = (size_t)h * DKK;

    uint32_t qf[8][4];
    {
        size_t r0 = ((size_t)(b * SS + q0 + wm + tg)) * DD + hb;
        size_t r8 = r0 + (size_t)8 * DD;
        #pragma unroll
        for (int ks = 0; ks < 8; ks++) {
            int c = ks * 8 + tig;
            qf[ks][0] = __float_as_uint(q[r0 + c    ] * 0.125f);
            qf[ks][1] = __float_as_uint(q[r8 + c    ] * 0.125f);
            qf[ks][2] = __float_as_uint(q[r0 + c + 4] * 0.125f);
            qf[ks][3] = __float_as_uint(q[r8 + c + 4] * 0.125f);
        }
    }

    float oacc[8][4];
    #pragma unroll
    for (int ni = 0; ni < 8; ni++)
        #pragma unroll
        for (int r = 0; r < 4; r++) oacc[ni][r] = 0.f;
    float m0 = -1e30f, m1 = -1e30f, l0 = 0.f, l1 = 0.f;

    const size_t kvbase = ((size_t)(b * SS)) * DD + hb;

    #define KV_PREFETCH(bf, kt) do {                                          \
        const float* kg = k + kvbase + (size_t)((kt) * 64) * DD;              \
        const float* vg = v + kvbase + (size_t)((kt) * 64) * DD;              \
        uint32_t kb = smem_u32(Ks[bf]);                                       \
        uint32_t vb = smem_u32(Vs[bf]);                                       \
        _Pragma("unroll")                                                     \
        for (int i = 0; i < 8; i++) {                                         \
            int e = tid + i * 128;                                            \
            int row = e >> 4, c = e & 15;                                     \
            cp16(kb + row * (KSS * 4) + c * 16, kg + (size_t)row * DD + c * 4);\
            cp16(vb + row * (VSS * 4) + c * 16, vg + (size_t)row * DD + c * 4);\
        }                                                                     \
        asm volatile("cp.async.commit_group;");                               \
    } while (0)

    KV_PREFETCH(0, 0);

    const int NT = SS / 64;
    for (int kt = 0; kt < NT; kt++) {
        int cur = kt & 1;
        asm volatile("cp.async.wait_group 0;");
        __syncthreads();
        if (kt + 1 < NT) KV_PREFETCH(cur ^ 1, kt + 1);

        float sacc[8][4];
        #pragma unroll
        for (int ni = 0; ni < 8; ni++)
            #pragma unroll
            for (int r = 0; r < 4; r++) sacc[ni][r] = 0.f;

        const float* Kc = Ks[cur];
        #pragma unroll
        for (int ks = 0; ks < 8; ks++) {
            int kc = ks * 8;
            #pragma unroll
            for (int ni = 0; ni < 8; ni++) {
                uint32_t bf2[2];
                int cn = ni * 8 + tg;
                bf2[0] = __float_as_uint(Kc[cn * KSS + kc + tig]);
                bf2[1] = __float_as_uint(Kc[cn * KSS + kc + 4 + tig]);
                mma_tf32(sacc[ni], qf[ks], bf2);
            }
        }

        float rmax0 = -1e30f, rmax1 = -1e30f;
        #pragma unroll
        for (int ni = 0; ni < 8; ni++) {
            rmax0 = fmaxf(rmax0, fmaxf(sacc[ni][0], sacc[ni][1]));
            rmax1 = fmaxf(rmax1, fmaxf(sacc[ni][2], sacc[ni][3]));
        }
        #pragma unroll
        for (int d = 1; d < 4; d <<= 1) {
            rmax0 = fmaxf(rmax0, __shfl_xor_sync(0xFFFFFFFFu, rmax0, d));
            rmax1 = fmaxf(rmax1, __shfl_xor_sync(0xFFFFFFFFu, rmax1, d));
        }
        float nm0 = fmaxf(m0, rmax0);
        float nm1 = fmaxf(m1, rmax1);
        float corr0 = __expf(m0 - nm0);
        float corr1 = __expf(m1 - nm1);

        float rsum0 = 0.f, rsum1 = 0.f;
        #pragma unroll
        for (int ni = 0; ni < 8; ni++) {
            float p0 = __expf(sacc[ni][0] - nm0);
            float p1 = __expf(sacc[ni][1] - nm0);
            float p2 = __expf(sacc[ni][2] - nm1);
            float p3 = __expf(sacc[ni][3] - nm1);
            rsum0 += p0 + p1;
            rsum1 += p2 + p3;
            float* pr0 = Ps + (wm + tg) * PSS + ni * 8 + 2 * tig;
            float* pr1 = Ps + (wm + tg + 8) * PSS + ni * 8 + 2 * tig;
            pr0[0] = p0; pr0[1] = p1;
            pr1[0] = p2; pr1[1] = p3;
        }
        #pragma unroll
        for (int d = 1; d < 4; d <<= 1) {
            rsum0 += __shfl_xor_sync(0xFFFFFFFFu, rsum0, d);
            rsum1 += __shfl_xor_sync(0xFFFFFFFFu, rsum1, d);
        }
        l0 = l0 * corr0 + rsum0;
        l1 = l1 * corr1 + rsum1;
        m0 = nm0; m1 = nm1;

        #pragma unroll
        for (int ni = 0; ni < 8; ni++) {
            oacc[ni][0] *= corr0; oacc[ni][1] *= corr0;
            oacc[ni][2] *= corr1; oacc[ni][3] *= corr1;
        }

        __syncwarp();

        const float* Vc = Vs[cur];
        #pragma unroll
        for (int ks = 0; ks < 8; ks++) {
            int kc = ks * 8;
            uint32_t af[4];
            af[0] = __float_as_uint(Ps[(wm + tg    ) * PSS + kc + tig]);
            af[1] = __float_as_uint(Ps[(wm + tg + 8) * PSS + kc + tig]);
            af[2] = __float_as_uint(Ps[(wm + tg    ) * PSS + kc + 4 + tig]);
            af[3] = __float_as_uint(Ps[(wm + tg + 8) * PSS + kc + 4 + tig]);
            #pragma unroll
            for (int ni = 0; ni < 8; ni++) {
                uint32_t bf2[2];
                int cn = ni * 8 + tg;
                bf2[0] = __float_as_uint(Vc[(kc + tig    ) * VSS + cn]);
                bf2[1] = __float_as_uint(Vc[(kc + 4 + tig) * VSS + cn]);
                mma_tf32(oacc[ni], af, bf2);
            }
        }
        __syncwarp();
    }

    float inv0 = 1.f / l0;
    float inv1 = 1.f / l1;
    size_t r0 = ((size_t)(b * SS + q0 + wm + tg)) * DD + hb;
    size_t r8 = r0 + (size_t)8 * DD;
    #pragma unroll
    for (int ni = 0; ni < 8; ni++) {
        int c = ni * 8 + 2 * tig;
        *(__half2*)(o + r0 + c) =
            __floats2half2_rn(oacc[ni][0] * inv0, oacc[ni][1] * inv0);
        *(__half2*)(o + r8 + c) =
            __floats2half2_rn(oacc[ni][2] * inv1, oacc[ni][3] * inv1);
    }
    #undef KV_PREFETCH
}

// ---------------------------------------------------------------------------
// Host orchestration
// ---------------------------------------------------------------------------
extern "C" void kernel_launch(void* const* d_in, const int* in_sizes, int n_in,
                              void* d_out, int out_size)
{
    (void)in_sizes; (void)n_in; (void)out_size;

    const float* x  = (const float*)d_in[0];
    const float* wq = (const float*)d_in[1];
    const float* bq = (const float*)d_in[2];
    const float* wk = (const float*)d_in[3];
    const float* bk = (const float*)d_in[4];
    const float* wv = (const float*)d_in[5];
    const float* bv = (const float*)d_in[6];
    const float* wo = (const float*)d_in[7];
    const float* bo = (const float*)d_in[8];
    const float* w1 = (const float*)d_in[9];
    const float* b1 = (const float*)d_in[10];
    const float* w2 = (const float*)d_in[11];
    const float* b2 = (const float*)d_in[12];
    const float* g1 = (const float*)d_in[13];
    const float* g2 = (const float*)d_in[14];
    float* out = (float*)d_out;

    __half *ph, *po, *ph2, *pff;
    float  *pq, *pk, *pv, *px2;
    uint32_t *ppwq, *ppwk, *ppwv, *ppwo, *ppw1, *ppw2;
    cudaGetSymbolAddress((void**)&ph,  g_h);
    cudaGetSymbolAddress((void**)&pq,  g_q);
    cudaGetSymbolAddress((void**)&pk,  g_k);
    cudaGetSymbolAddress((void**)&pv,  g_v);
    cudaGetSymbolAddress((void**)&po,  g_o);
    cudaGetSymbolAddress((void**)&px2, g_x2);
    cudaGetSymbolAddress((void**)&ph2, g_h2);
    cudaGetSymbolAddress((void**)&pff, g_ff);
    cudaGetSymbolAddress((void**)&ppwq, g_pwq);
    cudaGetSymbolAddress((void**)&ppwk, g_pwk);
    cudaGetSymbolAddress((void**)&ppwv, g_pwv);
    cudaGetSymbolAddress((void**)&ppwo, g_pwo);
    cudaGetSymbolAddress((void**)&ppw1, g_pw1);
    cudaGetSymbolAddress((void**)&ppw2, g_pw2);

    cudaFuncSetAttribute(attn_mma,
        cudaFuncAttributeMaxDynamicSharedMemorySize, ATTN_SMEM);
    cudaFuncSetAttribute(gemm_h,
        cudaFuncAttributeMaxDynamicSharedMemorySize, GEMM_SMEM);
    cudaFuncSetAttribute(gemm_qkv,
        cudaFuncAttributeMaxDynamicSharedMemorySize, GEMM_SMEM);

    dim3 gD(DD / BN,   MM / BM);   // (8, 32)
    dim3 gF(DFFF / BN, MM / BM);   // (32, 32)

    // 1) pack weights to fp16 pair-interleaved layout
    pack_w_kernel<<<(DD/2 * DD)   / 256, 256>>>(wq, ppwq, DD, DD);
    pack_w_kernel<<<(DD/2 * DD)   / 256, 256>>>(wk, ppwk, DD, DD);
    pack_w_kernel<<<(DD/2 * DD)   / 256, 256>>>(wv, ppwv, DD, DD);
    pack_w_kernel<<<(DD/2 * DD)   / 256, 256>>>(wo, ppwo, DD, DD);
    pack_w_kernel<<<(DD/2 * DFFF) / 256, 256>>>(w1, ppw1, DD, DFFF);
    pack_w_kernel<<<(DFFF/2 * DD) / 256, 256>>>(w2, ppw2, DFFF, DD);

    // 2) h = rmsnorm(x, g1)  -> half
    rmsnorm_h_kernel<<<MM, 256>>>(x, g1, ph);

    // 3) fused QKV projections (q,k,v fp32; v tf32-rounded)
    gemm_qkv<<<dim3(24, MM / BM), 256, GEMM_SMEM>>>(
        ph, ppwq, ppwk, ppwv, bq, bk, bv, pq, pk, pv);

    // 4) RoPE (q,k fp32, tf32-rounded outputs)
    rope_kernel<<<(MM * HH * 32) / 256, 256>>>(pq, pk);

    // 5) attention -> o half
    attn_mma<<<dim3(SS / 64, HH, BB), 128, ATTN_SMEM>>>(pq, pk, pv, po);

    // 6) x2 = x + o @ wo + bo   (fp32 out)
    gemm_h<<<gD, 256, GEMM_SMEM>>>(po, ppwo, bo, x, px2, DD, DD, 2, 0);

    // 7) h2 = rmsnorm(x2, g2) -> half
    rmsnorm_h_kernel<<<MM, 256>>>(px2, g2, ph2);

    // 8) ff = relu(h2 @ w1 + b1) -> half
    gemm_h<<<gF, 256, GEMM_SMEM>>>(ph2, ppw1, b1, nullptr, pff, DFFF, DD, 1, 2);

    // 9) out = x2 + ff @ w2 + b2   (fp32 out)
    gemm_h<<<gD, 256, GEMM_SMEM>>>(pff, ppw2, b2, px2, out, DD, DFFF, 2, 0);
}

// round 11
// speedup vs baseline: 2.1772x; 1.2833x over previous
#include <cuda_runtime.h>
#include <cuda_fp16.h>
#include <cstdint>
#include <math.h>

// Problem constants
#define BB   2
#define SS   2048
#define DD   1024
#define HH   16
#define DKK  64
#define DFFF 4096
#define MM   (BB * SS)          // 4096 rows
#define EPSF 1.1920929e-07f

// ---------------------------------------------------------------------------
// Scratch (device globals — no cudaMalloc allowed)
// ---------------------------------------------------------------------------
__device__ __half g_h  [MM * DD];    // rmsnorm1 out
__device__ __half g_q  [MM * DD];    // q (half, post-RoPE pre-scaled by 1/8)
__device__ __half g_k  [MM * DD];    // k (half, post-RoPE)
__device__ __half g_v  [MM * DD];    // v (half)
__device__ __half g_o  [MM * DD];    // attention out
__device__ float  g_x2 [MM * DD];
__device__ __half g_h2 [MM * DD];    // rmsnorm2 out
__device__ __half g_ff [MM * DFFF];  // relu FFN mid
// fp16 pair-packed weights: [K/2][N] of half2 (low = even-k)
__device__ uint32_t g_pwq[DD * DD / 2];
__device__ uint32_t g_pwk[DD * DD / 2];
__device__ uint32_t g_pwv[DD * DD / 2];
__device__ uint32_t g_pwo[DD * DD / 2];
__device__ uint32_t g_pw1[DD * DFFF / 2];
__device__ uint32_t g_pw2[DFFF * DD / 2];

// ---------------------------------------------------------------------------
// helpers
// ---------------------------------------------------------------------------
__device__ __forceinline__ uint32_t smem_u32(const void* p) {
    uint32_t a;
    asm("{ .reg .u64 t; cvta.to.shared.u64 t, %1; cvt.u32.u64 %0, t; }"
        : "=r"(a) : "l"(p));
    return a;
}
__device__ __forceinline__ void cp16(uint32_t saddr, const void* g) {
    asm volatile("cp.async.cg.shared.global [%0], [%1], 16;" :: "r"(saddr), "l"(g));
}
__device__ __forceinline__ void mma_f16(
    float* c, const uint32_t* a, const uint32_t* b)
{
    asm volatile(
        "mma.sync.aligned.m16n8k16.row.col.f32.f16.f16.f32 "
        "{%0,%1,%2,%3}, {%4,%5,%6,%7}, {%8,%9}, {%0,%1,%2,%3};"
        : "+f"(c[0]), "+f"(c[1]), "+f"(c[2]), "+f"(c[3])
        : "r"(a[0]), "r"(a[1]), "r"(a[2]), "r"(a[3]), "r"(b[0]), "r"(b[1]));
}
__device__ __forceinline__ uint32_t h2_bits(__half2 h) {
    return *reinterpret_cast<uint32_t*>(&h);
}
#define LDSM_X4T(r0, r1, r2, r3, addr)                                        \
    asm volatile("ldmatrix.sync.aligned.m8n8.x4.trans.shared.b16 "            \
        "{%0,%1,%2,%3}, [%4];"                                                \
        : "=r"(r0), "=r"(r1), "=r"(r2), "=r"(r3) : "r"(addr))

// ---------------------------------------------------------------------------
// Weight pack: fp32 [K][N] -> half2 [K/2][N]  (low half = even k)
// ---------------------------------------------------------------------------
__global__ void __launch_bounds__(256) pack_w_kernel(
    const float* __restrict__ w, uint32_t* __restrict__ out, int K, int N)
{
    int i  = blockIdx.x * 256 + threadIdx.x;
    int k2 = i / N;
    int n  = i - k2 * N;
    float a = w[(size_t)(2 * k2)     * N + n];
    float b = w[(size_t)(2 * k2 + 1) * N + n];
    out[i] = h2_bits(__floats2half2_rn(a, b));
}

// ---------------------------------------------------------------------------
// fp16 mma.sync GEMM (proven R10): C = A[M,K] @ W[K,N] + bias (+relu/+res)
// A: [M][K] half. W: pair-packed half2 [K/2][N].
// CTA 128x128, BK=32, 256 threads (2x4 warps, 64x32 warp tile),
// 4-stage cp.async pipeline, 2 CTAs/SM.
// epi: 0=bias, 1=bias+relu, 2=bias+residual ; outm: 0=fp32, 2=half
// ---------------------------------------------------------------------------
#define BM 128
#define BN 128
#define BK 32
#define ASTRH 40
#define BNP 136
#define A_WORDS (BM * ASTRH / 2)
#define B_WORDS (16 * BNP)
#define STG_WORDS (A_WORDS + B_WORDS)
#define NSTG 4
#define GEMM_SMEM (NSTG * STG_WORDS * 4)

__device__ __forceinline__ void gemm_core(
    const __half* __restrict__ A, const uint32_t* __restrict__ Bp,
    const float* __restrict__ bias, const float* __restrict__ res,
    void* __restrict__ C, int Nd, int Kd, int brow, int bcol,
    int epi, int outm, uint32_t* sm)
{
    const int tid  = threadIdx.x;
    const int lane = tid & 31;
    const int wid  = tid >> 5;
    const int warp_m = (wid >> 2) * 64;
    const int warp_n = (wid & 3) * 32;
    const int KT = Kd / BK;

    const int tg  = lane >> 2;
    const int tig = lane & 3;

    float acc[4][4][4];
    #pragma unroll
    for (int i = 0; i < 4; i++)
        #pragma unroll
        for (int j = 0; j < 4; j++)
            #pragma unroll
            for (int r = 0; r < 4; r++) acc[i][j][r] = 0.f;

    #define COPY_STAGE(s, kt) do {                                             \
        __half*   sA = (__half*)(sm + (s) * STG_WORDS);                        \
        uint32_t* sB = sm + (s) * STG_WORDS + A_WORDS;                         \
        int k0 = (kt) * BK;                                                    \
        _Pragma("unroll")                                                      \
        for (int i = 0; i < 2; i++) {                                          \
            int e = tid + i * 256;                                             \
            int m = e >> 2, c8 = (e & 3) << 3;                                 \
            cp16(smem_u32(sA + m * ASTRH + c8),                                \
                 A + (size_t)(brow + m) * Kd + k0 + c8);                       \
        }                                                                      \
        _Pragma("unroll")                                                      \
        for (int i = 0; i < 2; i++) {                                          \
            int e = tid + i * 256;                                             \
            int r = e >> 5, c4 = (e & 31) << 2;                                \
            cp16(smem_u32(sB + r * BNP + c4),                                  \
                 Bp + ((size_t)(k0 >> 1) + r) * Nd + bcol + c4);               \
        }                                                                      \
        asm volatile("cp.async.commit_group;");                                \
    } while (0)

    COPY_STAGE(0, 0);
    COPY_STAGE(1, 1);
    COPY_STAGE(2, 2);

    for (int kt = 0; kt < KT; kt++) {
        int s = kt & (NSTG - 1);
        if (kt + 3 < KT) COPY_STAGE((kt + 3) & (NSTG - 1), kt + 3);

        int ahead = KT - 1 - kt;
        if (ahead >= 3)      asm volatile("cp.async.wait_group 3;");
        else if (ahead == 2) asm volatile("cp.async.wait_group 2;");
        else if (ahead == 1) asm volatile("cp.async.wait_group 1;");
        else                 asm volatile("cp.async.wait_group 0;");
        __syncthreads();

        const __half*   As = (const __half*)(sm + s * STG_WORDS);
        const uint32_t* Bs = sm + s * STG_WORDS + A_WORDS;

        #pragma unroll
        for (int ks = 0; ks < 2; ks++) {
            uint32_t af[4][4], bf[4][2];
            #pragma unroll
            for (int mi = 0; mi < 4; mi++) {
                int rm = warp_m + mi * 16 + tg;
                const __half* ap = As + rm * ASTRH + ks * 16 + 2 * tig;
                af[mi][0] = *(const uint32_t*)(ap);
                af[mi][1] = *(const uint32_t*)(ap + 8 * ASTRH);
                af[mi][2] = *(const uint32_t*)(ap + 8);
                af[mi][3] = *(const uint32_t*)(ap + 8 * ASTRH + 8);
            }
            #pragma unroll
            for (int ni = 0; ni < 4; ni++) {
                int cn = warp_n + ni * 8 + tg;
                bf[ni][0] = Bs[(ks * 8 + tig    ) * BNP + cn];
                bf[ni][1] = Bs[(ks * 8 + tig + 4) * BNP + cn];
            }
            #pragma unroll
            for (int mi = 0; mi < 4; mi++)
                #pragma unroll
                for (int ni = 0; ni < 4; ni++)
                    mma_f16(acc[mi][ni], af[mi], bf[ni]);
        }
        __syncthreads();
    }

    #pragma unroll
    for (int mi = 0; mi < 4; mi++) {
        int row0 = brow + warp_m + mi * 16 + tg;
        #pragma unroll
        for (int ni = 0; ni < 4; ni++) {
            int col = bcol + warp_n + ni * 8 + tig * 2;
            float2 bv = *(const float2*)(bias + col);
            #pragma unroll
            for (int half_ = 0; half_ < 2; half_++) {
                int row = row0 + half_ * 8;
                float v0 = acc[mi][ni][half_ * 2 + 0] + bv.x;
                float v1 = acc[mi][ni][half_ * 2 + 1] + bv.y;
                if (epi == 1) { v0 = fmaxf(v0, 0.f); v1 = fmaxf(v1, 0.f); }
                if (epi == 2) {
                    float2 rv = *(const float2*)(res + (size_t)row * Nd + col);
                    v0 += rv.x; v1 += rv.y;
                }
                if (outm == 2) {
                    *(__half2*)((__half*)C + (size_t)row * Nd + col) =
                        __floats2half2_rn(v0, v1);
                } else {
                    float2 o2; o2.x = v0; o2.y = v1;
                    *(float2*)((float*)C + (size_t)row * Nd + col) = o2;
                }
            }
        }
    }
    #undef COPY_STAGE
}

__global__ void __launch_bounds__(256, 2) gemm_h(
    const __half* __restrict__ A, const uint32_t* __restrict__ Bp,
    const float* __restrict__ bias, const float* __restrict__ res,
    void* __restrict__ C, int Nd, int Kd, int epi, int outm)
{
    extern __shared__ uint32_t sm[];
    gemm_core(A, Bp, bias, res, C, Nd, Kd,
              blockIdx.y * BM, blockIdx.x * BN, epi, outm, sm);
}

// Fused QKV: grid.x in [0,24); nsel = x>>3. All outputs half.
__global__ void __launch_bounds__(256, 2) gemm_qkv(
    const __half* __restrict__ A,
    const uint32_t* __restrict__ Bq, const uint32_t* __restrict__ Bk,
    const uint32_t* __restrict__ Bv,
    const float* __restrict__ bq, const float* __restrict__ bk,
    const float* __restrict__ bv,
    __half* __restrict__ Cq, __half* __restrict__ Ck, __half* __restrict__ Cv)
{
    extern __shared__ uint32_t sm[];
    int nsel = blockIdx.x >> 3;
    int bcol = (blockIdx.x & 7) * BN;
    const uint32_t* B = (nsel == 0) ? Bq : (nsel == 1) ? Bk : Bv;
    const float* bi   = (nsel == 0) ? bq : (nsel == 1) ? bk : bv;
    __half* C         = (nsel == 0) ? Cq : (nsel == 1) ? Ck : Cv;
    gemm_core(A, B, bi, nullptr, C, DD, DD,
              blockIdx.y * BM, bcol, 0, 2, sm);
}

// ---------------------------------------------------------------------------
// RMSNorm: fp32 in, half out
// ---------------------------------------------------------------------------
__global__ void __launch_bounds__(256) rmsnorm_h_kernel(
    const float* __restrict__ x, const float* __restrict__ g,
    __half* __restrict__ out)
{
    int row = blockIdx.x;
    const float4* xr = (const float4*)(x + (size_t)row * DD);
    float4 xv = xr[threadIdx.x];
    float ss = xv.x * xv.x + xv.y * xv.y + xv.z * xv.z + xv.w * xv.w;
    #pragma unroll
    for (int off = 16; off > 0; off >>= 1)
        ss += __shfl_xor_sync(0xFFFFFFFFu, ss, off);
    __shared__ float sred[8];
    __shared__ float sscale;
    int warp = threadIdx.x >> 5;
    if ((threadIdx.x & 31) == 0) sred[warp] = ss;
    __syncthreads();
    if (threadIdx.x == 0) {
        float t = 0.f;
        #pragma unroll
        for (int i = 0; i < 8; i++) t += sred[i];
        sscale = rsqrtf(t / (float)DD + EPSF);
    }
    __syncthreads();
    float sc = sscale;
    float4 gv = ((const float4*)g)[threadIdx.x];
    uint2 u;
    u.x = h2_bits(__floats2half2_rn(xv.x * sc * gv.x, xv.y * sc * gv.y));
    u.y = h2_bits(__floats2half2_rn(xv.z * sc * gv.z, xv.w * sc * gv.w));
    ((uint2*)(out + (size_t)row * DD))[threadIdx.x] = u;
}

// ---------------------------------------------------------------------------
// RoPE on half q,k; q additionally scaled by 1/sqrt(dk) = 0.125
// ---------------------------------------------------------------------------
#define LOG2_10000_OVER_32 0.41524101186092029f
__global__ void rope_kernel(__half* __restrict__ q, __half* __restrict__ k)
{
    int idx = blockIdx.x * blockDim.x + threadIdx.x;
    int j   = idx & 31;
    int h   = (idx >> 5) & (HH - 1);
    int row = idx >> 9;
    int s   = row & (SS - 1);
    float inv_freq = exp2f(-(float)j * LOG2_10000_OVER_32);
    float ang = (float)s * inv_freq;
    float sn, cs;
    sincosf(ang, &sn, &cs);
    size_t base = (size_t)row * DD + h * DKK + j;
    float q1 = __half2float(q[base]), q2 = __half2float(q[base + 32]);
    q[base]      = __float2half_rn((q1 * cs - q2 * sn) * 0.125f);
    q[base + 32] = __float2half_rn((q2 * cs + q1 * sn) * 0.125f);
    float k1 = __half2float(k[base]), k2 = __half2float(k[base + 32]);
    k[base]      = __float2half_rn(k1 * cs - k2 * sn);
    k[base + 32] = __float2half_rn(k2 * cs + k1 * sn);
}

// ---------------------------------------------------------------------------
// Flash attention, fp16 m16n8k16.
// CTA: 64 queries x one (b,h). 4 warps. K/V 64x64 half tiles, double-buffered.
// QK^T: scalar half2 B-fragment loads. PV: ldmatrix.x4.trans on V.
// P round-trips smem as half2. Softmax state fp32.
// ---------------------------------------------------------------------------
#define KSH 72   // halves per K smem row
#define VSH 72
#define PSH 72
#define AOFF_K0 0
#define AOFF_K1 (64 * KSH)
#define AOFF_V0 (2 * 64 * KSH)
#define AOFF_V1 (2 * 64 * KSH + 64 * VSH)
#define AOFF_P  (2 * 64 * KSH + 2 * 64 * VSH)
#define ATTN_SMEM ((2 * 64 * KSH + 2 * 64 * VSH + 64 * PSH) * 2)

__global__ void __launch_bounds__(128, 3) attn_mma(
    const __half* __restrict__ q, const __half* __restrict__ k,
    const __half* __restrict__ v, __half* __restrict__ o)
{
    extern __shared__ __half smh[];
    __half* Ks[2] = { smh + AOFF_K0, smh + AOFF_K1 };
    __half* Vs[2] = { smh + AOFF_V0, smh + AOFF_V1 };
    __half* Ps    = smh + AOFF_P;

    const int tid  = threadIdx.x;
    const int lane = tid & 31;
    const int wid  = tid >> 5;
    const int wm   = wid * 16;
    const int tg   = lane >> 2;
    const int tig  = lane & 3;
    // ldmatrix.x4.trans lane mapping for V
    const int lm = lane >> 3;      // matrix 0..3
    const int lr = lane & 7;       // row within matrix
    const uint32_t vfrag_off =
        (uint32_t)(((lm & 1) * 8 + lr) * VSH + (lm >> 1) * 8) * 2;

    const int h  = blockIdx.y;
    const int b  = blockIdx.z;
    const int q0 = blockIdx.x * 64;
    const size_t hb = (size_t)h * DKK;

    // Q fragments (half2 words; q pre-scaled by 0.125 in RoPE)
    uint32_t qf[4][4];
    {
        size_t r0 = ((size_t)(b * SS + q0 + wm + tg)) * DD + hb;
        size_t r8 = r0 + (size_t)8 * DD;
        #pragma unroll
        for (int ks = 0; ks < 4; ks++) {
            int c = ks * 16 + 2 * tig;
            qf[ks][0] = *(const uint32_t*)(q + r0 + c);
            qf[ks][1] = *(const uint32_t*)(q + r8 + c);
            qf[ks][2] = *(const uint32_t*)(q + r0 + c + 8);
            qf[ks][3] = *(const uint32_t*)(q + r8 + c + 8);
        }
    }

    float oacc[8][4];
    #pragma unroll
    for (int ni = 0; ni < 8; ni++)
        #pragma unroll
        for (int r = 0; r < 4; r++) oacc[ni][r] = 0.f;
    float m0 = -1e30f, m1 = -1e30f, l0 = 0.f, l1 = 0.f;

    const size_t kvbase = ((size_t)(b * SS)) * DD + hb;

    // K/V tile: 64 rows x 64 halves = 8 cp16 chunks per row; 4 iters each
    #define KV_PREFETCH(bf, kt) do {                                          \
        const __half* kg = k + kvbase + (size_t)((kt) * 64) * DD;             \
        const __half* vg = v + kvbase + (size_t)((kt) * 64) * DD;             \
        uint32_t kb = smem_u32(Ks[bf]);                                       \
        uint32_t vb = smem_u32(Vs[bf]);                                       \
        _Pragma("unroll")                                                     \
        for (int i = 0; i < 4; i++) {                                         \
            int e = tid + i * 128;                                            \
            int row = e >> 3, c = e & 7;                                      \
            cp16(kb + (row * KSH + c * 8) * 2, kg + (size_t)row * DD + c * 8);\
            cp16(vb + (row * VSH + c * 8) * 2, vg + (size_t)row * DD + c * 8);\
        }                                                                     \
        asm volatile("cp.async.commit_group;");                               \
    } while (0)

    KV_PREFETCH(0, 0);

    const int NT = SS / 64;
    for (int kt = 0; kt < NT; kt++) {
        int cur = kt & 1;
        asm volatile("cp.async.wait_group 0;");
        __syncthreads();
        if (kt + 1 < NT) KV_PREFETCH(cur ^ 1, kt + 1);

        // ---- S = Q @ K^T (fp16, 32 MMAs) ----
        float sacc[8][4];
        #pragma unroll
        for (int ni = 0; ni < 8; ni++)
            #pragma unroll
            for (int r = 0; r < 4; r++) sacc[ni][r] = 0.f;

        const __half* Kc = Ks[cur];
        #pragma unroll
        for (int ks = 0; ks < 4; ks++) {
            #pragma unroll
            for (int ni = 0; ni < 8; ni++) {
                int cn = ni * 8 + tg;
                uint32_t bf2[2];
                bf2[0] = *(const uint32_t*)(Kc + cn * KSH + ks * 16 + 2 * tig);
                bf2[1] = *(const uint32_t*)(Kc + cn * KSH + ks * 16 + 8 + 2 * tig);
                mma_f16(sacc[ni], qf[ks], bf2);
            }
        }

        // ---- online softmax ----
        float rmax0 = -1e30f, rmax1 = -1e30f;
        #pragma unroll
        for (int ni = 0; ni < 8; ni++) {
            rmax0 = fmaxf(rmax0, fmaxf(sacc[ni][0], sacc[ni][1]));
            rmax1 = fmaxf(rmax1, fmaxf(sacc[ni][2], sacc[ni][3]));
        }
        #pragma unroll
        for (int d = 1; d < 4; d <<= 1) {
            rmax0 = fmaxf(rmax0, __shfl_xor_sync(0xFFFFFFFFu, rmax0, d));
            rmax1 = fmaxf(rmax1, __shfl_xor_sync(0xFFFFFFFFu, rmax1, d));
        }
        float nm0 = fmaxf(m0, rmax0);
        float nm1 = fmaxf(m1, rmax1);
        float corr0 = __expf(m0 - nm0);
        float corr1 = __expf(m1 - nm1);

        float rsum0 = 0.f, rsum1 = 0.f;
        #pragma unroll
        for (int ni = 0; ni < 8; ni++) {
            float p0 = __expf(sacc[ni][0] - nm0);
            float p1 = __expf(sacc[ni][1] - nm0);
            float p2 = __expf(sacc[ni][2] - nm1);
            float p3 = __expf(sacc[ni][3] - nm1);
            rsum0 += p0 + p1;
            rsum1 += p2 + p3;
            *(__half2*)(Ps + (wm + tg    ) * PSH + ni * 8 + 2 * tig) =
                __floats2half2_rn(p0, p1);
            *(__half2*)(Ps + (wm + tg + 8) * PSH + ni * 8 + 2 * tig) =
                __floats2half2_rn(p2, p3);
        }
        #pragma unroll
        for (int d = 1; d < 4; d <<= 1) {
            rsum0 += __shfl_xor_sync(0xFFFFFFFFu, rsum0, d);
            rsum1 += __shfl_xor_sync(0xFFFFFFFFu, rsum1, d);
        }
        l0 = l0 * corr0 + rsum0;
        l1 = l1 * corr1 + rsum1;
        m0 = nm0; m1 = nm1;

        #pragma unroll
        for (int ni = 0; ni < 8; ni++) {
            oacc[ni][0] *= corr0; oacc[ni][1] *= corr0;
            oacc[ni][2] *= corr1; oacc[ni][3] *= corr1;
        }

        __syncwarp();

        // ---- O += P @ V (fp16; V fragments via ldmatrix.trans) ----
        uint32_t vmBase = smem_u32(Vs[cur]) + vfrag_off;
        #pragma unroll
        for (int ks = 0; ks < 4; ks++) {
            uint32_t af[4];
            const __half* pr = Ps + (wm + tg) * PSH + ks * 16 + 2 * tig;
            af[0] = *(const uint32_t*)(pr);
            af[1] = *(const uint32_t*)(pr + 8 * PSH);
            af[2] = *(const uint32_t*)(pr + 8);
            af[3] = *(const uint32_t*)(pr + 8 * PSH + 8);
            #pragma unroll
            for (int nip = 0; nip < 4; nip++) {
                uint32_t b0a, b1a, b0b, b1b;
                LDSM_X4T(b0a, b1a, b0b, b1b,
                         vmBase + (uint32_t)(ks * 16 * VSH + nip * 16) * 2);
                uint32_t bA[2] = { b0a, b1a };
                uint32_t bB[2] = { b0b, b1b };
                mma_f16(oacc[2 * nip    ], af, bA);
                mma_f16(oacc[2 * nip + 1], af, bB);
            }
        }
        __syncwarp();
    }

    float inv0 = 1.f / l0;
    float inv1 = 1.f / l1;
    size_t r0 = ((size_t)(b * SS + q0 + wm + tg)) * DD + hb;
    size_t r8 = r0 + (size_t)8 * DD;
    #pragma unroll
    for (int ni = 0; ni < 8; ni++) {
        int c = ni * 8 + 2 * tig;
        *(__half2*)(o + r0 + c) =
            __floats2half2_rn(oacc[ni][0] * inv0, oacc[ni][1] * inv0);
        *(__half2*)(o + r8 + c) =
            __floats2half2_rn(oacc[ni][2] * inv1, oacc[ni][3] * inv1);
    }
    #undef KV_PREFETCH
}

// ---------------------------------------------------------------------------
// Host orchestration
// ---------------------------------------------------------------------------
extern "C" void kernel_launch(void* const* d_in, const int* in_sizes, int n_in,
                              void* d_out, int out_size)
{
    (void)in_sizes; (void)n_in; (void)out_size;

    const float* x  = (const float*)d_in[0];
    const float* wq = (const float*)d_in[1];
    const float* bq = (const float*)d_in[2];
    const float* wk = (const float*)d_in[3];
    const float* bk = (const float*)d_in[4];
    const float* wv = (const float*)d_in[5];
    const float* bv = (const float*)d_in[6];
    const float* wo = (const float*)d_in[7];
    const float* bo = (const float*)d_in[8];
    const float* w1 = (const float*)d_in[9];
    const float* b1 = (const float*)d_in[10];
    const float* w2 = (const float*)d_in[11];
    const float* b2 = (const float*)d_in[12];
    const float* g1 = (const float*)d_in[13];
    const float* g2 = (const float*)d_in[14];
    float* out = (float*)d_out;

    __half *ph, *pq, *pk, *pv, *po, *ph2, *pff;
    float  *px2;
    uint32_t *ppwq, *ppwk, *ppwv, *ppwo, *ppw1, *ppw2;
    cudaGetSymbolAddress((void**)&ph,  g_h);
    cudaGetSymbolAddress((void**)&pq,  g_q);
    cudaGetSymbolAddress((void**)&pk,  g_k);
    cudaGetSymbolAddress((void**)&pv,  g_v);
    cudaGetSymbolAddress((void**)&po,  g_o);
    cudaGetSymbolAddress((void**)&px2, g_x2);
    cudaGetSymbolAddress((void**)&ph2, g_h2);
    cudaGetSymbolAddress((void**)&pff, g_ff);
    cudaGetSymbolAddress((void**)&ppwq, g_pwq);
    cudaGetSymbolAddress((void**)&ppwk, g_pwk);
    cudaGetSymbolAddress((void**)&ppwv, g_pwv);
    cudaGetSymbolAddress((void**)&ppwo, g_pwo);
    cudaGetSymbolAddress((void**)&ppw1, g_pw1);
    cudaGetSymbolAddress((void**)&ppw2, g_pw2);

    cudaFuncSetAttribute(attn_mma,
        cudaFuncAttributeMaxDynamicSharedMemorySize, ATTN_SMEM);
    cudaFuncSetAttribute(gemm_h,
        cudaFuncAttributeMaxDynamicSharedMemorySize, GEMM_SMEM);
    cudaFuncSetAttribute(gemm_qkv,
        cudaFuncAttributeMaxDynamicSharedMemorySize, GEMM_SMEM);

    dim3 gD(DD / BN,   MM / BM);   // (8, 32)
    dim3 gF(DFFF / BN, MM / BM);   // (32, 32)

    // 1) pack weights to fp16 pair-interleaved layout
    pack_w_kernel<<<(DD/2 * DD)   / 256, 256>>>(wq, ppwq, DD, DD);
    pack_w_kernel<<<(DD/2 * DD)   / 256, 256>>>(wk, ppwk, DD, DD);
    pack_w_kernel<<<(DD/2 * DD)   / 256, 256>>>(wv, ppwv, DD, DD);
    pack_w_kernel<<<(DD/2 * DD)   / 256, 256>>>(wo, ppwo, DD, DD);
    pack_w_kernel<<<(DD/2 * DFFF) / 256, 256>>>(w1, ppw1, DD, DFFF);
    pack_w_kernel<<<(DFFF/2 * DD) / 256, 256>>>(w2, ppw2, DFFF, DD);

    // 2) h = rmsnorm(x, g1) -> half
    rmsnorm_h_kernel<<<MM, 256>>>(x, g1, ph);

    // 3) fused QKV projections -> half q,k,v
    gemm_qkv<<<dim3(24, MM / BM), 256, GEMM_SMEM>>>(
        ph, ppwq, ppwk, ppwv, bq, bk, bv, pq, pk, pv);

    // 4) RoPE on half q,k (q scaled by 0.125)
    rope_kernel<<<(MM * HH * 32) / 256, 256>>>(pq, pk);

    // 5) attention (fp16) -> o half
    attn_mma<<<dim3(SS / 64, HH, BB), 128, ATTN_SMEM>>>(pq, pk, pv, po);

    // 6) x2 = x + o @ wo + bo   (fp32 out)
    gemm_h<<<gD, 256, GEMM_SMEM>>>(po, ppwo, bo, x, px2, DD, DD, 2, 0);

    // 7) h2 = rmsnorm(x2, g2) -> half
    rmsnorm_h_kernel<<<MM, 256>>>(px2, g2, ph2);

    // 8) ff = relu(h2 @ w1 + b1) -> half
    gemm_h<<<gF, 256, GEMM_SMEM>>>(ph2, ppw1, b1, nullptr, pff, DFFF, DD, 1, 2);

    // 9) out = x2 + ff @ w2 + b2   (fp32 out)
    gemm_h<<<gD, 256, GEMM_SMEM>>>(pff, ppw2, b2, px2, out, DD, DFFF, 2, 0);
}